// round 2
// baseline (speedup 1.0000x reference)
#include <cuda_runtime.h>
#include <math.h>
#include <stdint.h>

#define NN   65536
#define GG   1024
#define NPG  64
#define VV   32
#define HH   128
#define EE   1048576
#define NOUT 10

// ---------------- scratch (device globals; no allocation allowed) ----------------
__device__ float d_h   [NN*HH];
__device__ float d_hw  [NN*HH];
__device__ float d_h2  [NN*HH];
__device__ float d_aff1[NN*HH];
__device__ float d_aff [NN*HH];
__device__ float d_inv [NN];
__device__ int   d_cnt [NN];
__device__ int   d_off [NN+1];
__device__ int   d_cur [NN];
__device__ int   d_bsum[64];
__device__ unsigned char d_esrc[EE];
__device__ float d_vn  [GG*VV*HH];
__device__ float d_vn1 [GG*VV*HH];
__device__ float d_vn2 [GG*VV*HH];
__device__ float d_gf  [GG*HH];
__device__ float d_gf2 [GG*HH];

// ---------------- generic M x 128 x 128 GEMM:  C = [relu](A @ W + bias) ----------------
// block: 256 threads -> 64 rows x 128 cols per block. W and A tile staged in shared.
template<int RELU, int BIAS>
__global__ void __launch_bounds__(256) k_gemm128(const float* __restrict__ A,
                                                 const float* __restrict__ W,
                                                 const float* __restrict__ bias,
                                                 float* __restrict__ C, int M)
{
    extern __shared__ float sm[];
    float4* Ws4 = (float4*)sm;               // 128 x 32 float4  (64 KB)
    float4* As4 = (float4*)(sm + 128*128);   // 64  x 32 float4  (32 KB)

    const int tid = threadIdx.x;
    const int tx  = tid & 31;     // col group: cols 4*tx .. 4*tx+3
    const int ty  = tid >> 5;     // row group: rows ty*8 .. ty*8+7
    const int row0 = blockIdx.x * 64;
    (void)M;

    const float4* W4 = (const float4*)W;
    const float4* A4 = (const float4*)(A + (size_t)row0 * 128);
    for (int i = tid; i < 4096; i += 256) Ws4[i] = W4[i];
    for (int i = tid; i < 2048; i += 256) As4[i] = A4[i];
    __syncthreads();

    float4 acc[8];
#pragma unroll
    for (int j = 0; j < 8; j++) acc[j] = make_float4(0.f, 0.f, 0.f, 0.f);

#pragma unroll 2
    for (int kq = 0; kq < 32; kq++) {
        float4 w0 = Ws4[(kq*4+0)*32 + tx];
        float4 w1 = Ws4[(kq*4+1)*32 + tx];
        float4 w2 = Ws4[(kq*4+2)*32 + tx];
        float4 w3 = Ws4[(kq*4+3)*32 + tx];
#pragma unroll
        for (int j = 0; j < 8; j++) {
            float4 a = As4[(ty*8+j)*32 + kq];   // broadcast within warp
            acc[j].x += a.x*w0.x + a.y*w1.x + a.z*w2.x + a.w*w3.x;
            acc[j].y += a.x*w0.y + a.y*w1.y + a.z*w2.y + a.w*w3.y;
            acc[j].z += a.x*w0.z + a.y*w1.z + a.z*w2.z + a.w*w3.z;
            acc[j].w += a.x*w0.w + a.y*w1.w + a.z*w2.w + a.w*w3.w;
        }
    }

    float4 bv = make_float4(0.f, 0.f, 0.f, 0.f);
    if (BIAS) bv = ((const float4*)bias)[tx];
    float4* C4 = (float4*)(C + (size_t)row0 * 128);
#pragma unroll
    for (int j = 0; j < 8; j++) {
        float4 r = acc[j];
        r.x += bv.x; r.y += bv.y; r.z += bv.z; r.w += bv.w;
        if (RELU) { r.x = fmaxf(r.x, 0.f); r.y = fmaxf(r.y, 0.f);
                    r.z = fmaxf(r.z, 0.f); r.w = fmaxf(r.w, 0.f); }
        C4[(ty*8+j)*32 + tx] = r;
    }
}

// ---------------- edge pipeline (edge_index is INT32: jax x64 is disabled) -------------
__global__ void k_zero2(int* cnt, int* cur) {
    int i = blockIdx.x * blockDim.x + threadIdx.x;
    cnt[i] = 0; cur[i] = 0;
}

__global__ void k_count(const int* __restrict__ ei, int* __restrict__ cnt) {
    int e = blockIdx.x * blockDim.x + threadIdx.x;
    int dst = ei[EE + e];
    if ((unsigned)dst < NN) atomicAdd(&cnt[dst], 1);
}

__global__ void k_inv(const int* __restrict__ cnt, float* __restrict__ inv) {
    int i = blockIdx.x * blockDim.x + threadIdx.x;
    inv[i] = rsqrtf((float)(cnt[i] + 1));   // +1 self loop, deg >= 1 always
}

__global__ void __launch_bounds__(1024) k_scan1(const int* __restrict__ cnt,
                                                int* __restrict__ off,
                                                int* __restrict__ bsum) {
    __shared__ int s[1024];
    int b = blockIdx.x, t = threadIdx.x;
    int i = b * 1024 + t;
    s[t] = cnt[i];
    __syncthreads();
    for (int d = 1; d < 1024; d <<= 1) {
        int v = (t >= d) ? s[t-d] : 0;
        __syncthreads();
        s[t] += v;
        __syncthreads();
    }
    off[i + 1] = s[t];
    if (t == 1023) bsum[b] = s[t];
}

__global__ void k_scan2(int* bsum) {
    __shared__ int s[64];
    int t = threadIdx.x;
    s[t] = bsum[t];
    __syncthreads();
    for (int d = 1; d < 64; d <<= 1) {
        int v = (t >= d) ? s[t-d] : 0;
        __syncthreads();
        s[t] += v;
        __syncthreads();
    }
    bsum[t] = s[t];
}

__global__ void k_scan3(int* __restrict__ off, const int* __restrict__ bsum) {
    int i = blockIdx.x * blockDim.x + threadIdx.x;
    int b = i >> 10;
    if (b > 0) off[i + 1] += bsum[b - 1];
    if (i == 0) off[0] = 0;
}

__global__ void k_scatter(const int* __restrict__ ei, const int* __restrict__ off,
                          int* __restrict__ cur, unsigned char* __restrict__ esrc) {
    int e = blockIdx.x * blockDim.x + threadIdx.x;
    int s = ei[e];
    int d = ei[EE + e];
    if ((unsigned)d >= NN) return;
    int pos = off[d] + atomicAdd(&cur[d], 1);
    esrc[pos] = (unsigned char)(s & 63);
}

// ---------------- GCN aggregation (gather per graph, deterministic via bucket sort) ----
__global__ void __launch_bounds__(128) k_gcn_agg(const float* __restrict__ hw,
                                                 const float* __restrict__ inv,
                                                 const float* __restrict__ b_gcn,
                                                 const int* __restrict__ off,
                                                 const unsigned char* __restrict__ esrc,
                                                 float* __restrict__ h2)
{
    __shared__ float ssrc[NPG * HH];        // 32 KB, pre-scaled source rows: hw[s]*inv[s]
    __shared__ unsigned char se[8192];      // graph's edge bucket (local src ids)
    __shared__ int soff[NPG + 1];

    const int g = blockIdx.x, tid = threadIdx.x;
    const int nbase = g * NPG;

    const float4* hw4 = (const float4*)(hw + (size_t)nbase * HH);
    float4* ssrc4 = (float4*)ssrc;
    for (int i = tid; i < NPG*HH/4; i += 128) {
        int r = i >> 5;
        float iv = inv[nbase + r];
        float4 t = hw4[i];
        t.x *= iv; t.y *= iv; t.z *= iv; t.w *= iv;
        ssrc4[i] = t;
    }
    if (tid <= NPG) soff[tid] = off[nbase + tid];
    __syncthreads();

    const int ge0  = soff[0];
    const int gcnt = soff[NPG] - ge0;
    const int stg  = (gcnt < 8192) ? gcnt : 8192;   // 8192 = 256 sigma; never exceeded
    for (int i = tid; i < stg; i += 128) se[i] = esrc[ge0 + i];
    __syncthreads();

    // canonicalize each destination bucket (determinism independent of atomic order)
    if (tid < NPG) {
        int a = soff[tid] - ge0, b = soff[tid+1] - ge0;
        if (b > stg) b = stg;
        for (int i = a + 1; i < b; i++) {
            unsigned char key = se[i];
            int j = i - 1;
            while (j >= a && se[j] > key) { se[j+1] = se[j]; j--; }
            se[j+1] = key;
        }
    }
    __syncthreads();

    const float bg = b_gcn[tid];
    for (int r = 0; r < NPG; r++) {
        int e0 = soff[r] - ge0, e1 = soff[r+1] - ge0;
        float acc = 0.f;
        for (int e = e0; e < e1; e++) {
            int s = (e < stg) ? (int)se[e] : (int)esrc[ge0 + e];
            acc += ssrc[s * HH + tid];
        }
        int node = nbase + r;
        float iv = inv[node];
        // total = inv[d]*sum_s(hw[s]*inv[s]) + hw[d]*inv[d]^2 ; ssrc[r] = hw[d]*inv[d]
        float val = iv * (acc + ssrc[r * HH + tid]);
        h2[(size_t)node * HH + tid] = fmaxf(val + bg, 0.f);
    }
}

// ---------------- per-graph attention + weighted scatter pool ----------------
// shared: hgs 32KB | affs 32KB | vembT (128 x 33, padded, transposed) | sew 8KB
__global__ void __launch_bounds__(128) k_att(const float* __restrict__ h2,
                                             const float* __restrict__ aff,
                                             const float* __restrict__ vemb,
                                             const float* __restrict__ eweights,
                                             float* __restrict__ vn_out)
{
    extern __shared__ float sm[];
    float* hgs   = sm;                       // 64*128
    float* affs  = sm + NPG*HH;              // 64*128
    float* vembT = sm + 2*NPG*HH;            // 128*33 (k-major, padded)
    float* sew   = vembT + HH*33;            // 64*32

    const int g = blockIdx.x, tid = threadIdx.x;

    const float4* hg4 = (const float4*)(h2  + (size_t)g*NPG*HH);
    const float4* af4 = (const float4*)(aff + (size_t)g*NPG*HH);
    float4* hgs4  = (float4*)hgs;
    float4* affs4 = (float4*)affs;
    for (int i = tid; i < NPG*HH/4; i += 128) { hgs4[i] = hg4[i]; affs4[i] = af4[i]; }

    const float* vg = vemb + (size_t)g*VV*HH;
    for (int i = tid; i < VV*HH; i += 128) {
        int v = i >> 7, k = i & 127;
        vembT[k*33 + v] = vg[i];
    }
    __syncthreads();

    // att[n][v] = (aff[n] . vemb[v]) / sqrt(128);  ew = edge_weights * (1 + sigmoid(att))
    const int v  = tid & 31;
    const int ng = tid >> 5;
    const float* ew_g = eweights + (size_t)g*NPG*VV;
    const float scale = 0.08838834764831845f;   // 1/sqrt(128)

    for (int c = 0; c < 4; c++) {
        int n0 = ng*16 + c*4;
        float acc0 = 0.f, acc1 = 0.f, acc2 = 0.f, acc3 = 0.f;
#pragma unroll 4
        for (int kq = 0; kq < 32; kq++) {
            float4 a0 = affs4[(n0+0)*32 + kq];
            float4 a1 = affs4[(n0+1)*32 + kq];
            float4 a2 = affs4[(n0+2)*32 + kq];
            float4 a3 = affs4[(n0+3)*32 + kq];
            float w0 = vembT[(kq*4+0)*33 + v];
            float w1 = vembT[(kq*4+1)*33 + v];
            float w2 = vembT[(kq*4+2)*33 + v];
            float w3 = vembT[(kq*4+3)*33 + v];
            acc0 += a0.x*w0 + a0.y*w1 + a0.z*w2 + a0.w*w3;
            acc1 += a1.x*w0 + a1.y*w1 + a1.z*w2 + a1.w*w3;
            acc2 += a2.x*w0 + a2.y*w1 + a2.z*w2 + a2.w*w3;
            acc3 += a3.x*w0 + a3.y*w1 + a3.z*w2 + a3.w*w3;
        }
        float accs[4] = {acc0, acc1, acc2, acc3};
#pragma unroll
        for (int j = 0; j < 4; j++) {
            int n = n0 + j;
            float att = accs[j] * scale;
            float sg = 1.f / (1.f + expf(-att));
            sew[n*32 + v] = ew_g[n*32 + v] * (1.f + sg);
        }
    }
    __syncthreads();

    // row-normalize ew over v
    if (tid < NPG) {
        float rs = 0.f;
        for (int v2 = 0; v2 < VV; v2++) rs += sew[tid*32 + v2];
        float denom = (rs == 0.f) ? 1.f : rs;
        float ivr = 1.f / denom;
        for (int v2 = 0; v2 < VV; v2++) sew[tid*32 + v2] *= ivr;
    }
    __syncthreads();

    // vn[v][h] = sum_n ew[n][v] * hg[n][h]
    const int c4  = tid & 31;   // col group (4 floats)
    const int vgp = tid >> 5;   // 8 v's per thread, tiled by 4
    for (int vt = 0; vt < 2; vt++) {
        int vb = vgp*8 + vt*4;
        float4 acc[4];
#pragma unroll
        for (int u = 0; u < 4; u++) acc[u] = make_float4(0.f, 0.f, 0.f, 0.f);
        for (int n = 0; n < NPG; n++) {
            float4 hv = hgs4[n*32 + c4];
#pragma unroll
            for (int u = 0; u < 4; u++) {
                float w = sew[n*32 + vb + u];
                acc[u].x += w*hv.x; acc[u].y += w*hv.y;
                acc[u].z += w*hv.z; acc[u].w += w*hv.w;
            }
        }
#pragma unroll
        for (int u = 0; u < 4; u++)
            ((float4*)(vn_out + (size_t)(g*VV + vb + u)*HH))[c4] = acc[u];
    }
}

// ---------------- graph feature mean over V ----------------
__global__ void k_gf(const float* __restrict__ vn2, float* __restrict__ gf) {
    int i = blockIdx.x * blockDim.x + threadIdx.x;   // GG*HH
    int g = i >> 7, hcol = i & 127;
    float s = 0.f;
    for (int v = 0; v < VV; v++) s += vn2[(size_t)(g*VV + v)*HH + hcol];
    gf[i] = s * (1.f / 32.f);
}

// ---------------- output head (128 -> 10) ----------------
__global__ void __launch_bounds__(128) k_head(const float* __restrict__ gf2,
                                              const float* __restrict__ W,
                                              const float* __restrict__ b,
                                              float* __restrict__ out) {
    __shared__ float row[HH];
    int g = blockIdx.x;
    row[threadIdx.x] = gf2[(size_t)g*HH + threadIdx.x];
    __syncthreads();
    if (threadIdx.x < NOUT) {
        float acc = b[threadIdx.x];
        for (int k = 0; k < HH; k++) acc += row[k] * W[k*NOUT + threadIdx.x];
        out[g*NOUT + threadIdx.x] = acc;
    }
}

// ---------------- launcher ----------------
extern "C" void kernel_launch(void* const* d_in, const int* in_sizes, int n_in,
                              void* d_out, int out_size)
{
    (void)in_sizes; (void)n_in; (void)out_size;
    const float* x        = (const float*)d_in[0];
    const int*   ei       = (const int*)d_in[1];      // int32! (jax x64 disabled)
    const float* eweights = (const float*)d_in[3];
    const float* vemb     = (const float*)d_in[4];
    const float* W_emb  = (const float*)d_in[5];  const float* b_emb  = (const float*)d_in[6];
    const float* W_gcn  = (const float*)d_in[7];  const float* b_gcn  = (const float*)d_in[8];
    const float* aff_W1 = (const float*)d_in[9];  const float* aff_b1 = (const float*)d_in[10];
    const float* aff_W2 = (const float*)d_in[11]; const float* aff_b2 = (const float*)d_in[12];
    const float* vn_W1  = (const float*)d_in[13]; const float* vn_b1  = (const float*)d_in[14];
    const float* vn_W2  = (const float*)d_in[15]; const float* vn_b2  = (const float*)d_in[16];
    const float* mlp_W1 = (const float*)d_in[17]; const float* mlp_b1 = (const float*)d_in[18];
    const float* mlp_W2 = (const float*)d_in[19]; const float* mlp_b2 = (const float*)d_in[20];
    float* out = (float*)d_out;

    float *p_h, *p_hw, *p_h2, *p_aff1, *p_aff, *p_inv, *p_vn, *p_vn1, *p_vn2, *p_gf, *p_gf2;
    int *p_cnt, *p_off, *p_cur, *p_bsum;
    unsigned char* p_esrc;
    cudaGetSymbolAddress((void**)&p_h,    d_h);
    cudaGetSymbolAddress((void**)&p_hw,   d_hw);
    cudaGetSymbolAddress((void**)&p_h2,   d_h2);
    cudaGetSymbolAddress((void**)&p_aff1, d_aff1);
    cudaGetSymbolAddress((void**)&p_aff,  d_aff);
    cudaGetSymbolAddress((void**)&p_inv,  d_inv);
    cudaGetSymbolAddress((void**)&p_cnt,  d_cnt);
    cudaGetSymbolAddress((void**)&p_off,  d_off);
    cudaGetSymbolAddress((void**)&p_cur,  d_cur);
    cudaGetSymbolAddress((void**)&p_bsum, d_bsum);
    cudaGetSymbolAddress((void**)&p_esrc, d_esrc);
    cudaGetSymbolAddress((void**)&p_vn,   d_vn);
    cudaGetSymbolAddress((void**)&p_vn1,  d_vn1);
    cudaGetSymbolAddress((void**)&p_vn2,  d_vn2);
    cudaGetSymbolAddress((void**)&p_gf,   d_gf);
    cudaGetSymbolAddress((void**)&p_gf2,  d_gf2);

    const int GEMM_SMEM = (128*128 + 64*128) * (int)sizeof(float);   // 96 KB
    const int ATT_SMEM  = (2*NPG*HH + HH*33 + NPG*VV) * (int)sizeof(float);
    cudaFuncSetAttribute(k_gemm128<0,1>, cudaFuncAttributeMaxDynamicSharedMemorySize, GEMM_SMEM);
    cudaFuncSetAttribute(k_gemm128<0,0>, cudaFuncAttributeMaxDynamicSharedMemorySize, GEMM_SMEM);
    cudaFuncSetAttribute(k_gemm128<1,1>, cudaFuncAttributeMaxDynamicSharedMemorySize, GEMM_SMEM);
    cudaFuncSetAttribute(k_att,          cudaFuncAttributeMaxDynamicSharedMemorySize, ATT_SMEM);

    // 1) node embedding + GCN linear
    k_gemm128<0,1><<<NN/64, 256, GEMM_SMEM>>>(x,   W_emb, b_emb,   p_h,  NN);
    k_gemm128<0,0><<<NN/64, 256, GEMM_SMEM>>>(p_h, W_gcn, nullptr, p_hw, NN);

    // 2) edge bucketing by destination node (deterministic aggregation)
    k_zero2  <<<NN/256, 256>>>(p_cnt, p_cur);
    k_count  <<<EE/256, 256>>>(ei, p_cnt);
    k_inv    <<<NN/256, 256>>>(p_cnt, p_inv);
    k_scan1  <<<64, 1024>>>(p_cnt, p_off, p_bsum);
    k_scan2  <<<1, 64>>>(p_bsum);
    k_scan3  <<<NN/256, 256>>>(p_off, p_bsum);
    k_scatter<<<EE/256, 256>>>(ei, p_off, p_cur, p_esrc);

    // 3) GCN message aggregation + relu
    k_gcn_agg<<<GG, 128>>>(p_hw, p_inv, b_gcn, p_off, p_esrc, p_h2);

    // 4) affinity MLP
    k_gemm128<1,1><<<NN/64, 256, GEMM_SMEM>>>(p_h2,   aff_W1, aff_b1, p_aff1, NN);
    k_gemm128<0,1><<<NN/64, 256, GEMM_SMEM>>>(p_aff1, aff_W2, aff_b2, p_aff,  NN);

    // 5) attention vs virtual nodes + weighted pool
    k_att<<<GG, 128, ATT_SMEM>>>(p_h2, p_aff, vemb, eweights, p_vn);

    // 6) virtual-node MLP
    k_gemm128<1,1><<<GG*VV/64, 256, GEMM_SMEM>>>(p_vn,  vn_W1, vn_b1, p_vn1, GG*VV);
    k_gemm128<0,1><<<GG*VV/64, 256, GEMM_SMEM>>>(p_vn1, vn_W2, vn_b2, p_vn2, GG*VV);

    // 7) mean over V, output MLP
    k_gf  <<<GG*HH/256, 256>>>(p_vn2, p_gf);
    k_gemm128<1,1><<<GG/64, 256, GEMM_SMEM>>>(p_gf, mlp_W1, mlp_b1, p_gf2, GG);
    k_head<<<GG, 128>>>(p_gf2, mlp_W2, mlp_b2, out);
}

// round 4
// speedup vs baseline: 1.0182x; 1.0182x over previous
#include <cuda_runtime.h>
#include <cuda_bf16.h>
#include <math.h>
#include <stdint.h>

#define NN   65536
#define GG   1024
#define NPG  64
#define VV   32
#define HH   128
#define EE   1048576
#define NOUT 10

// ---------------- scratch (device globals; no allocation allowed) ----------------
__device__ float d_h   [NN*HH];
__device__ float d_hw  [NN*HH];
__device__ float d_h2  [NN*HH];
__device__ float d_aff1[NN*HH];
__device__ float d_aff [NN*HH];
__device__ float d_inv [NN];
__device__ int   d_cnt [NN];
__device__ int   d_off [NN+1];
__device__ int   d_cur [NN];
__device__ int   d_bsum[64];
__device__ unsigned char d_esrc[EE];
__device__ float d_vn  [GG*VV*HH];
__device__ float d_vn1 [GG*VV*HH];
__device__ float d_vn2 [GG*VV*HH];
__device__ float d_gf  [GG*HH];
__device__ float d_gf2 [GG*HH];
__device__ __nv_bfloat16 d_wt0[7*128*128];   // Wt hi (transposed, [n][k])
__device__ __nv_bfloat16 d_wt1[7*128*128];   // Wt lo

// ================= helpers =================
__device__ __forceinline__ uint32_t smem_u32(const void* p) {
    uint32_t a;
    asm("{ .reg .u64 t; cvta.to.shared.u64 t, %1; cvt.u32.u64 %0, t; }" : "=r"(a) : "l"(p));
    return a;
}
__device__ __forceinline__ uint32_t pack_bf16x2(__nv_bfloat16 lo, __nv_bfloat16 hi) {
    return (uint32_t)__bfloat16_as_ushort(lo) | ((uint32_t)__bfloat16_as_ushort(hi) << 16);
}
// blocked K-major tile byte offset for (row r, col k), bf16, K=128, SW128 swizzle:
// atom = 8 rows x 64 bf16 (1024 B); 16 atom-rows contiguous, atom-col stride 16 KB
__device__ __forceinline__ uint32_t tile_off(int r, int k) {
    uint32_t base = ((((uint32_t)k >> 6) * 16u + ((uint32_t)r >> 3)) << 10)
                  + (((uint32_t)r & 7) << 7) + (((uint32_t)k & 63) << 1);
    return base ^ ((base >> 3) & 0x70);
}
// per-lane ldmatrix chunk address (must be 16B aligned: k multiple of 8)
__device__ __forceinline__ uint32_t frag_addr(uint32_t base, int r, int k) {
    return base + (((uint32_t)k >> 6) << 14) + (((uint32_t)r >> 3) << 10)
         + (((uint32_t)r & 7) << 7) + ((((uint32_t)k & 63) << 1) ^ (((uint32_t)r & 7) << 4));
}
__device__ __forceinline__ void ldsm4(uint32_t* r, uint32_t addr) {
    asm volatile("ldmatrix.sync.aligned.m8n8.x4.shared.b16 {%0,%1,%2,%3}, [%4];"
        : "=r"(r[0]), "=r"(r[1]), "=r"(r[2]), "=r"(r[3]) : "r"(addr));
}
__device__ __forceinline__ void mma16816(float* c, const uint32_t* a, const uint32_t* b) {
    asm volatile("mma.sync.aligned.m16n8k16.row.col.f32.bf16.bf16.f32 "
        "{%0,%1,%2,%3}, {%4,%5,%6,%7}, {%8,%9}, {%0,%1,%2,%3};"
        : "+f"(c[0]), "+f"(c[1]), "+f"(c[2]), "+f"(c[3])
        : "r"(a[0]), "r"(a[1]), "r"(a[2]), "r"(a[3]), "r"(b[0]), "r"(b[1]));
}

// ---------------- weight prep: transpose + bf16 hi/lo split ----------------
__global__ void __launch_bounds__(128) k_prep_w(
    const float* W0, const float* W1, const float* W2, const float* W3,
    const float* W4, const float* W5, const float* W6,
    __nv_bfloat16* wt0, __nv_bfloat16* wt1)
{
    extern __shared__ float s[];
    const float* Ws[7] = {W0, W1, W2, W3, W4, W5, W6};
    const float* W = Ws[blockIdx.x];
    for (int i = threadIdx.x; i < 16384; i += 128) s[i] = W[i];
    __syncthreads();
    const int n = threadIdx.x;
    uint32_t* o0 = (uint32_t*)(wt0 + (size_t)blockIdx.x * 16384 + n * 128);
    uint32_t* o1 = (uint32_t*)(wt1 + (size_t)blockIdx.x * 16384 + n * 128);
    for (int k = 0; k < 128; k += 2) {
        float v0 = s[k * 128 + n], v1 = s[(k + 1) * 128 + n];
        __nv_bfloat16 h0 = __float2bfloat16(v0), h1 = __float2bfloat16(v1);
        __nv_bfloat16 l0 = __float2bfloat16(v0 - __bfloat162float(h0));
        __nv_bfloat16 l1 = __float2bfloat16(v1 - __bfloat162float(h1));
        o0[k >> 1] = pack_bf16x2(h0, h1);
        o1[k >> 1] = pack_bf16x2(l0, l1);
    }
}

// ---------------- tensor-core GEMM: C[M,128] = [relu](A @ W + b), M%128==0 ------------
// bf16 2-split, 3 HMMA passes: A0B0 + A0B1 + A1B0; fp32 register accumulate.
#define SA0 0
#define SA1 32768
#define SB0 65536
#define SB1 98304
#define GSM_TOTAL 131072

template<int RELU, int BIAS>
__global__ void __launch_bounds__(256) k_mma_gemm(
    const float* __restrict__ A,
    const __nv_bfloat16* __restrict__ Wt0,
    const __nv_bfloat16* __restrict__ Wt1,
    const float* __restrict__ bias,
    float* __restrict__ C)
{
    extern __shared__ char smem[];
    const uint32_t sb = smem_u32(smem);
    const int tid = threadIdx.x, wid = tid >> 5, lid = tid & 31;
    const int row0 = blockIdx.x * 128;

    // A tile: 128 x 128 fp32 -> hi/lo bf16, blocked SW128 K-major
    const float4* A4 = (const float4*)(A + (size_t)row0 * 128);
    for (int i = tid; i < 4096; i += 256) {
        int r = i >> 5, k = (i & 31) << 2;
        float4 a = A4[i];
        __nv_bfloat16 hx = __float2bfloat16(a.x), hy = __float2bfloat16(a.y);
        __nv_bfloat16 hz = __float2bfloat16(a.z), hw = __float2bfloat16(a.w);
        __nv_bfloat16 lx = __float2bfloat16(a.x - __bfloat162float(hx));
        __nv_bfloat16 ly = __float2bfloat16(a.y - __bfloat162float(hy));
        __nv_bfloat16 lz = __float2bfloat16(a.z - __bfloat162float(hz));
        __nv_bfloat16 lw = __float2bfloat16(a.w - __bfloat162float(hw));
        uint32_t sw = tile_off(r, k);
        *(uint2*)(smem + SA0 + sw) = make_uint2(pack_bf16x2(hx, hy), pack_bf16x2(hz, hw));
        *(uint2*)(smem + SA1 + sw) = make_uint2(pack_bf16x2(lx, ly), pack_bf16x2(lz, lw));
    }
    // B tiles: pre-transposed/split Wt [n][k] bf16
    const uint2* B0g = (const uint2*)Wt0;
    const uint2* B1g = (const uint2*)Wt1;
    for (int i = tid; i < 4096; i += 256) {
        int n = i >> 5, k = (i & 31) << 2;
        uint32_t sw = tile_off(n, k);
        *(uint2*)(smem + SB0 + sw) = B0g[i];
        *(uint2*)(smem + SB1 + sw) = B1g[i];
    }
    __syncthreads();

    // warp tiling: 4 (M) x 2 (N) warps; warp tile 32 x 64
    const int m0w = (wid >> 1) * 32;
    const int n0w = (wid & 1) * 64;
    const int arow = m0w + (lid & 7) + ((lid >> 3) & 1) * 8;   // + mf*16
    const int akad = (lid >> 4) * 8;                            // k-chunk select
    const int brow0 = n0w + (lid & 7) + (lid >> 4) * 8;        // + q*16
    const int bkad = ((lid >> 3) & 1) * 8;

    float acc[2][8][4];
#pragma unroll
    for (int mf = 0; mf < 2; mf++)
#pragma unroll
        for (int nf = 0; nf < 8; nf++)
#pragma unroll
            for (int j = 0; j < 4; j++) acc[mf][nf][j] = 0.f;

    const uint32_t abase[3] = {sb + SA0, sb + SA0, sb + SA1};
    const uint32_t bbase[3] = {sb + SB0, sb + SB1, sb + SB0};
#pragma unroll
    for (int p = 0; p < 3; p++) {
        const uint32_t ab = abase[p], bb = bbase[p];
#pragma unroll
        for (int k0 = 0; k0 < 128; k0 += 16) {
            uint32_t a[2][4], b[4][4];
            ldsm4(a[0], frag_addr(ab, arow,      k0 + akad));
            ldsm4(a[1], frag_addr(ab, arow + 16, k0 + akad));
#pragma unroll
            for (int q = 0; q < 4; q++)
                ldsm4(b[q], frag_addr(bb, brow0 + q * 16, k0 + bkad));
#pragma unroll
            for (int mf = 0; mf < 2; mf++)
#pragma unroll
                for (int nf = 0; nf < 8; nf++)
                    mma16816(acc[mf][nf], a[mf], &b[nf >> 1][(nf & 1) * 2]);
        }
    }

    // epilogue: c-frag lane mapping rows l/4 (+8), cols (l&3)*2 (+1)
    const int crow = lid >> 2;
    const int ccol = (lid & 3) * 2;
#pragma unroll
    for (int mf = 0; mf < 2; mf++) {
        int gr = row0 + m0w + mf * 16 + crow;
        float* C0 = C + (size_t)gr * 128;
#pragma unroll
        for (int nf = 0; nf < 8; nf++) {
            int cn = n0w + nf * 8 + ccol;
            float2 bv = make_float2(0.f, 0.f);
            if (BIAS) bv = *(const float2*)(bias + cn);
            float2 v0 = make_float2(acc[mf][nf][0] + bv.x, acc[mf][nf][1] + bv.y);
            float2 v1 = make_float2(acc[mf][nf][2] + bv.x, acc[mf][nf][3] + bv.y);
            if (RELU) {
                v0.x = fmaxf(v0.x, 0.f); v0.y = fmaxf(v0.y, 0.f);
                v1.x = fmaxf(v1.x, 0.f); v1.y = fmaxf(v1.y, 0.f);
            }
            *(float2*)(C0 + cn)            = v0;
            *(float2*)(C0 + 8 * 128 + cn)  = v1;
        }
    }
}

// ---------------- edge pipeline (edge_index is INT32) -------------
__global__ void k_zero2(int* cnt, int* cur) {
    int i = blockIdx.x * blockDim.x + threadIdx.x;
    cnt[i] = 0; cur[i] = 0;
}
__global__ void k_count(const int* __restrict__ ei, int* __restrict__ cnt) {
    int e = blockIdx.x * blockDim.x + threadIdx.x;
    int dst = ei[EE + e];
    if ((unsigned)dst < NN) atomicAdd(&cnt[dst], 1);
}
__global__ void k_inv(const int* __restrict__ cnt, float* __restrict__ inv) {
    int i = blockIdx.x * blockDim.x + threadIdx.x;
    inv[i] = rsqrtf((float)(cnt[i] + 1));
}
__global__ void __launch_bounds__(1024) k_scan1(const int* __restrict__ cnt,
                                                int* __restrict__ off, int* __restrict__ bsum) {
    __shared__ int s[1024];
    int b = blockIdx.x, t = threadIdx.x;
    int i = b * 1024 + t;
    s[t] = cnt[i];
    __syncthreads();
    for (int d = 1; d < 1024; d <<= 1) {
        int v = (t >= d) ? s[t-d] : 0;
        __syncthreads();
        s[t] += v;
        __syncthreads();
    }
    off[i + 1] = s[t];
    if (t == 1023) bsum[b] = s[t];
}
__global__ void k_scan2(int* bsum) {
    __shared__ int s[64];
    int t = threadIdx.x;
    s[t] = bsum[t];
    __syncthreads();
    for (int d = 1; d < 64; d <<= 1) {
        int v = (t >= d) ? s[t-d] : 0;
        __syncthreads();
        s[t] += v;
        __syncthreads();
    }
    bsum[t] = s[t];
}
__global__ void k_scan3(int* __restrict__ off, const int* __restrict__ bsum) {
    int i = blockIdx.x * blockDim.x + threadIdx.x;
    int b = i >> 10;
    if (b > 0) off[i + 1] += bsum[b - 1];
    if (i == 0) off[0] = 0;
}
__global__ void k_scatter(const int* __restrict__ ei, const int* __restrict__ off,
                          int* __restrict__ cur, unsigned char* __restrict__ esrc) {
    int e = blockIdx.x * blockDim.x + threadIdx.x;
    int s = ei[e];
    int d = ei[EE + e];
    if ((unsigned)d >= NN) return;
    int pos = off[d] + atomicAdd(&cur[d], 1);
    esrc[pos] = (unsigned char)(s & 63);
}

// ---------------- GCN aggregation (deterministic via bucket sort) ----
__global__ void __launch_bounds__(128) k_gcn_agg(const float* __restrict__ hw,
                                                 const float* __restrict__ inv,
                                                 const float* __restrict__ b_gcn,
                                                 const int* __restrict__ off,
                                                 const unsigned char* __restrict__ esrc,
                                                 float* __restrict__ h2)
{
    __shared__ float ssrc[NPG * HH];
    __shared__ unsigned char se[8192];
    __shared__ int soff[NPG + 1];

    const int g = blockIdx.x, tid = threadIdx.x;
    const int nbase = g * NPG;

    const float4* hw4 = (const float4*)(hw + (size_t)nbase * HH);
    float4* ssrc4 = (float4*)ssrc;
    for (int i = tid; i < NPG*HH/4; i += 128) {
        int r = i >> 5;
        float iv = inv[nbase + r];
        float4 t = hw4[i];
        t.x *= iv; t.y *= iv; t.z *= iv; t.w *= iv;
        ssrc4[i] = t;
    }
    if (tid <= NPG) soff[tid] = off[nbase + tid];
    __syncthreads();

    const int ge0  = soff[0];
    const int gcnt = soff[NPG] - ge0;
    const int stg  = (gcnt < 8192) ? gcnt : 8192;
    for (int i = tid; i < stg; i += 128) se[i] = esrc[ge0 + i];
    __syncthreads();

    if (tid < NPG) {
        int a = soff[tid] - ge0, b = soff[tid+1] - ge0;
        if (b > stg) b = stg;
        for (int i = a + 1; i < b; i++) {
            unsigned char key = se[i];
            int j = i - 1;
            while (j >= a && se[j] > key) { se[j+1] = se[j]; j--; }
            se[j+1] = key;
        }
    }
    __syncthreads();

    const float bg = b_gcn[tid];
    for (int r = 0; r < NPG; r++) {
        int e0 = soff[r] - ge0, e1 = soff[r+1] - ge0;
        float acc = 0.f;
        for (int e = e0; e < e1; e++) {
            int s = (e < stg) ? (int)se[e] : (int)esrc[ge0 + e];
            acc += ssrc[s * HH + tid];
        }
        int node = nbase + r;
        float iv = inv[node];
        float val = iv * (acc + ssrc[r * HH + tid]);
        h2[(size_t)node * HH + tid] = fmaxf(val + bg, 0.f);
    }
}

// ---------------- per-graph attention + weighted scatter pool ----------------
__global__ void __launch_bounds__(128) k_att(const float* __restrict__ h2,
                                             const float* __restrict__ aff,
                                             const float* __restrict__ vemb,
                                             const float* __restrict__ eweights,
                                             float* __restrict__ vn_out)
{
    extern __shared__ float sm[];
    float* hgs   = sm;
    float* affs  = sm + NPG*HH;
    float* vembT = sm + 2*NPG*HH;
    float* sew   = vembT + HH*33;

    const int g = blockIdx.x, tid = threadIdx.x;

    const float4* hg4 = (const float4*)(h2  + (size_t)g*NPG*HH);
    const float4* af4 = (const float4*)(aff + (size_t)g*NPG*HH);
    float4* hgs4  = (float4*)hgs;
    float4* affs4 = (float4*)affs;
    for (int i = tid; i < NPG*HH/4; i += 128) { hgs4[i] = hg4[i]; affs4[i] = af4[i]; }

    const float* vg = vemb + (size_t)g*VV*HH;
    for (int i = tid; i < VV*HH; i += 128) {
        int v = i >> 7, k = i & 127;
        vembT[k*33 + v] = vg[i];
    }
    __syncthreads();

    const int v  = tid & 31;
    const int ng = tid >> 5;
    const float* ew_g = eweights + (size_t)g*NPG*VV;
    const float scale = 0.08838834764831845f;

    for (int c = 0; c < 4; c++) {
        int n0 = ng*16 + c*4;
        float acc0 = 0.f, acc1 = 0.f, acc2 = 0.f, acc3 = 0.f;
#pragma unroll 4
        for (int kq = 0; kq < 32; kq++) {
            float4 a0 = affs4[(n0+0)*32 + kq];
            float4 a1 = affs4[(n0+1)*32 + kq];
            float4 a2 = affs4[(n0+2)*32 + kq];
            float4 a3 = affs4[(n0+3)*32 + kq];
            float w0 = vembT[(kq*4+0)*33 + v];
            float w1 = vembT[(kq*4+1)*33 + v];
            float w2 = vembT[(kq*4+2)*33 + v];
            float w3 = vembT[(kq*4+3)*33 + v];
            acc0 += a0.x*w0 + a0.y*w1 + a0.z*w2 + a0.w*w3;
            acc1 += a1.x*w0 + a1.y*w1 + a1.z*w2 + a1.w*w3;
            acc2 += a2.x*w0 + a2.y*w1 + a2.z*w2 + a2.w*w3;
            acc3 += a3.x*w0 + a3.y*w1 + a3.z*w2 + a3.w*w3;
        }
        float accs[4] = {acc0, acc1, acc2, acc3};
#pragma unroll
        for (int j = 0; j < 4; j++) {
            int n = n0 + j;
            float att = accs[j] * scale;
            float sg = 1.f / (1.f + expf(-att));
            sew[n*32 + v] = ew_g[n*32 + v] * (1.f + sg);
        }
    }
    __syncthreads();

    if (tid < NPG) {
        float rs = 0.f;
        for (int v2 = 0; v2 < VV; v2++) rs += sew[tid*32 + v2];
        float denom = (rs == 0.f) ? 1.f : rs;
        float ivr = 1.f / denom;
        for (int v2 = 0; v2 < VV; v2++) sew[tid*32 + v2] *= ivr;
    }
    __syncthreads();

    const int c4  = tid & 31;
    const int vgp = tid >> 5;
    for (int vt = 0; vt < 2; vt++) {
        int vb = vgp*8 + vt*4;
        float4 acc[4];
#pragma unroll
        for (int u = 0; u < 4; u++) acc[u] = make_float4(0.f, 0.f, 0.f, 0.f);
        for (int n = 0; n < NPG; n++) {
            float4 hv = hgs4[n*32 + c4];
#pragma unroll
            for (int u = 0; u < 4; u++) {
                float w = sew[n*32 + vb + u];
                acc[u].x += w*hv.x; acc[u].y += w*hv.y;
                acc[u].z += w*hv.z; acc[u].w += w*hv.w;
            }
        }
#pragma unroll
        for (int u = 0; u < 4; u++)
            ((float4*)(vn_out + (size_t)(g*VV + vb + u)*HH))[c4] = acc[u];
    }
}

// ---------------- graph feature mean over V ----------------
__global__ void k_gf(const float* __restrict__ vn2, float* __restrict__ gf) {
    int i = blockIdx.x * blockDim.x + threadIdx.x;
    int g = i >> 7, hcol = i & 127;
    float s = 0.f;
    for (int v = 0; v < VV; v++) s += vn2[(size_t)(g*VV + v)*HH + hcol];
    gf[i] = s * (1.f / 32.f);
}

// ---------------- output head (128 -> 10) ----------------
__global__ void __launch_bounds__(128) k_head(const float* __restrict__ gf2,
                                              const float* __restrict__ W,
                                              const float* __restrict__ b,
                                              float* __restrict__ out) {
    __shared__ float row[HH];
    int g = blockIdx.x;
    row[threadIdx.x] = gf2[(size_t)g*HH + threadIdx.x];
    __syncthreads();
    if (threadIdx.x < NOUT) {
        float acc = b[threadIdx.x];
        for (int k = 0; k < HH; k++) acc += row[k] * W[k*NOUT + threadIdx.x];
        out[g*NOUT + threadIdx.x] = acc;
    }
}

// ---------------- launcher ----------------
extern "C" void kernel_launch(void* const* d_in, const int* in_sizes, int n_in,
                              void* d_out, int out_size)
{
    (void)in_sizes; (void)n_in; (void)out_size;
    const float* x        = (const float*)d_in[0];
    const int*   ei       = (const int*)d_in[1];
    const float* eweights = (const float*)d_in[3];
    const float* vemb     = (const float*)d_in[4];
    const float* W_emb  = (const float*)d_in[5];  const float* b_emb  = (const float*)d_in[6];
    const float* W_gcn  = (const float*)d_in[7];  const float* b_gcn  = (const float*)d_in[8];
    const float* aff_W1 = (const float*)d_in[9];  const float* aff_b1 = (const float*)d_in[10];
    const float* aff_W2 = (const float*)d_in[11]; const float* aff_b2 = (const float*)d_in[12];
    const float* vn_W1  = (const float*)d_in[13]; const float* vn_b1  = (const float*)d_in[14];
    const float* vn_W2  = (const float*)d_in[15]; const float* vn_b2  = (const float*)d_in[16];
    const float* mlp_W1 = (const float*)d_in[17]; const float* mlp_b1 = (const float*)d_in[18];
    const float* mlp_W2 = (const float*)d_in[19]; const float* mlp_b2 = (const float*)d_in[20];
    float* out = (float*)d_out;

    float *p_h, *p_hw, *p_h2, *p_aff1, *p_aff, *p_inv, *p_vn, *p_vn1, *p_vn2, *p_gf, *p_gf2;
    int *p_cnt, *p_off, *p_cur, *p_bsum;
    unsigned char* p_esrc;
    __nv_bfloat16 *p_wt0, *p_wt1;
    cudaGetSymbolAddress((void**)&p_h,    d_h);
    cudaGetSymbolAddress((void**)&p_hw,   d_hw);
    cudaGetSymbolAddress((void**)&p_h2,   d_h2);
    cudaGetSymbolAddress((void**)&p_aff1, d_aff1);
    cudaGetSymbolAddress((void**)&p_aff,  d_aff);
    cudaGetSymbolAddress((void**)&p_inv,  d_inv);
    cudaGetSymbolAddress((void**)&p_cnt,  d_cnt);
    cudaGetSymbolAddress((void**)&p_off,  d_off);
    cudaGetSymbolAddress((void**)&p_cur,  d_cur);
    cudaGetSymbolAddress((void**)&p_bsum, d_bsum);
    cudaGetSymbolAddress((void**)&p_esrc, d_esrc);
    cudaGetSymbolAddress((void**)&p_vn,   d_vn);
    cudaGetSymbolAddress((void**)&p_vn1,  d_vn1);
    cudaGetSymbolAddress((void**)&p_vn2,  d_vn2);
    cudaGetSymbolAddress((void**)&p_gf,   d_gf);
    cudaGetSymbolAddress((void**)&p_gf2,  d_gf2);
    cudaGetSymbolAddress((void**)&p_wt0,  d_wt0);
    cudaGetSymbolAddress((void**)&p_wt1,  d_wt1);

    const int ATT_SMEM = (2*NPG*HH + HH*33 + NPG*VV) * (int)sizeof(float);
    cudaFuncSetAttribute(k_prep_w,        cudaFuncAttributeMaxDynamicSharedMemorySize, 65536);
    cudaFuncSetAttribute(k_mma_gemm<0,1>, cudaFuncAttributeMaxDynamicSharedMemorySize, GSM_TOTAL);
    cudaFuncSetAttribute(k_mma_gemm<0,0>, cudaFuncAttributeMaxDynamicSharedMemorySize, GSM_TOTAL);
    cudaFuncSetAttribute(k_mma_gemm<1,1>, cudaFuncAttributeMaxDynamicSharedMemorySize, GSM_TOTAL);
    cudaFuncSetAttribute(k_att,           cudaFuncAttributeMaxDynamicSharedMemorySize, ATT_SMEM);

    // 0) weight transpose + bf16 hi/lo split (7 x 128x128)
    k_prep_w<<<7, 128, 65536>>>(W_emb, W_gcn, aff_W1, aff_W2, vn_W1, vn_W2, mlp_W1,
                                p_wt0, p_wt1);
    #define WT0(i) (p_wt0 + (size_t)(i) * 16384)
    #define WT1(i) (p_wt1 + (size_t)(i) * 16384)

    // 1) node embedding + GCN linear
    k_mma_gemm<0,1><<<NN/128, 256, GSM_TOTAL>>>(x,   WT0(0), WT1(0), b_emb,   p_h);
    k_mma_gemm<0,0><<<NN/128, 256, GSM_TOTAL>>>(p_h, WT0(1), WT1(1), nullptr, p_hw);

    // 2) edge bucketing by destination node
    k_zero2  <<<NN/256, 256>>>(p_cnt, p_cur);
    k_count  <<<EE/256, 256>>>(ei, p_cnt);
    k_inv    <<<NN/256, 256>>>(p_cnt, p_inv);
    k_scan1  <<<64, 1024>>>(p_cnt, p_off, p_bsum);
    k_scan2  <<<1, 64>>>(p_bsum);
    k_scan3  <<<NN/256, 256>>>(p_off, p_bsum);
    k_scatter<<<EE/256, 256>>>(ei, p_off, p_cur, p_esrc);

    // 3) GCN message aggregation + relu
    k_gcn_agg<<<GG, 128>>>(p_hw, p_inv, b_gcn, p_off, p_esrc, p_h2);

    // 4) affinity MLP
    k_mma_gemm<1,1><<<NN/128, 256, GSM_TOTAL>>>(p_h2,   WT0(2), WT1(2), aff_b1, p_aff1);
    k_mma_gemm<0,1><<<NN/128, 256, GSM_TOTAL>>>(p_aff1, WT0(3), WT1(3), aff_b2, p_aff);

    // 5) attention vs virtual nodes + weighted pool
    k_att<<<GG, 128, ATT_SMEM>>>(p_h2, p_aff, vemb, eweights, p_vn);

    // 6) virtual-node MLP
    k_mma_gemm<1,1><<<GG*VV/128, 256, GSM_TOTAL>>>(p_vn,  WT0(4), WT1(4), vn_b1, p_vn1);
    k_mma_gemm<0,1><<<GG*VV/128, 256, GSM_TOTAL>>>(p_vn1, WT0(5), WT1(5), vn_b2, p_vn2);

    // 7) mean over V, output MLP
    k_gf<<<GG*HH/256, 256>>>(p_vn2, p_gf);
    k_mma_gemm<1,1><<<GG/128, 256, GSM_TOTAL>>>(p_gf, WT0(6), WT1(6), mlp_b1, p_gf2);
    k_head<<<GG, 128>>>(p_gf2, mlp_W2, mlp_b2, out);
}

// round 5
// speedup vs baseline: 1.1905x; 1.1693x over previous
#include <cuda_runtime.h>
#include <cuda_bf16.h>
#include <math.h>
#include <stdint.h>

#define NN   65536
#define GG   1024
#define NPG  64
#define VV   32
#define HH   128
#define EE   1048576
#define NOUT 10

// ---------------- scratch (device globals; no allocation allowed) ----------------
__device__ float d_hw  [NN*HH];
__device__ float d_h2  [NN*HH];
__device__ float d_aff [NN*HH];
__device__ int   d_cntm[GG*NPG*NPG];         // per-graph dense edge-count matrix (16 MB)
__device__ float d_vn  [GG*VV*HH];
__device__ float d_vn2 [GG*VV*HH];
__device__ float d_gf2 [GG*HH];
__device__ float d_wc  [HH*HH];              // W_emb @ W_gcn (fp32)
__device__ float d_bc  [HH];                 // b_emb @ W_gcn
__device__ __nv_bfloat16 d_wt0[6*HH*HH];     // weights hi (transposed [n][k])
__device__ __nv_bfloat16 d_wt1[6*HH*HH];     // weights lo

// ================= helpers =================
__device__ __forceinline__ uint32_t smem_u32(const void* p) {
    uint32_t a;
    asm("{ .reg .u64 t; cvta.to.shared.u64 t, %1; cvt.u32.u64 %0, t; }" : "=r"(a) : "l"(p));
    return a;
}
__device__ __forceinline__ uint32_t pack_bf16x2(__nv_bfloat16 lo, __nv_bfloat16 hi) {
    return (uint32_t)__bfloat16_as_ushort(lo) | ((uint32_t)__bfloat16_as_ushort(hi) << 16);
}
// blocked K-major tile byte offset for (row r, col k), bf16, K=128, SW128 swizzle
__device__ __forceinline__ uint32_t tile_off(int r, int k) {
    uint32_t base = ((((uint32_t)k >> 6) * 16u + ((uint32_t)r >> 3)) << 10)
                  + (((uint32_t)r & 7) << 7) + (((uint32_t)k & 63) << 1);
    return base ^ ((base >> 3) & 0x70);
}
// per-lane ldmatrix chunk address (k multiple of 8)
__device__ __forceinline__ uint32_t frag_addr(uint32_t base, int r, int k) {
    return base + (((uint32_t)k >> 6) << 14) + (((uint32_t)r >> 3) << 10)
         + (((uint32_t)r & 7) << 7) + ((((uint32_t)k & 63) << 1) ^ (((uint32_t)r & 7) << 4));
}
__device__ __forceinline__ void ldsm4(uint32_t* r, uint32_t addr) {
    asm volatile("ldmatrix.sync.aligned.m8n8.x4.shared.b16 {%0,%1,%2,%3}, [%4];"
        : "=r"(r[0]), "=r"(r[1]), "=r"(r[2]), "=r"(r[3]) : "r"(addr));
}
__device__ __forceinline__ void mma16816(float* c, const uint32_t* a, const uint32_t* b) {
    asm volatile("mma.sync.aligned.m16n8k16.row.col.f32.bf16.bf16.f32 "
        "{%0,%1,%2,%3}, {%4,%5,%6,%7}, {%8,%9}, {%0,%1,%2,%3};"
        : "+f"(c[0]), "+f"(c[1]), "+f"(c[2]), "+f"(c[3])
        : "r"(a[0]), "r"(a[1]), "r"(a[2]), "r"(a[3]), "r"(b[0]), "r"(b[1]));
}

// smem layout for GEMM/MLP kernels
#define SA0 0
#define SA1 32768
#define SB0 65536
#define SB1 98304
#define GSM_TOTAL 131072

// stage fp32 A tile (128x128) -> bf16 hi/lo split, swizzled
__device__ __forceinline__ void stage_A(char* smem, const float* __restrict__ A,
                                        int row0, int tid) {
    const float4* A4 = (const float4*)(A + (size_t)row0 * 128);
    for (int i = tid; i < 4096; i += 256) {
        int r = i >> 5, k = (i & 31) << 2;
        float4 a = A4[i];
        __nv_bfloat16 hx = __float2bfloat16(a.x), hy = __float2bfloat16(a.y);
        __nv_bfloat16 hz = __float2bfloat16(a.z), hw = __float2bfloat16(a.w);
        __nv_bfloat16 lx = __float2bfloat16(a.x - __bfloat162float(hx));
        __nv_bfloat16 ly = __float2bfloat16(a.y - __bfloat162float(hy));
        __nv_bfloat16 lz = __float2bfloat16(a.z - __bfloat162float(hz));
        __nv_bfloat16 lw = __float2bfloat16(a.w - __bfloat162float(hw));
        uint32_t sw = tile_off(r, k);
        *(uint2*)(smem + SA0 + sw) = make_uint2(pack_bf16x2(hx, hy), pack_bf16x2(hz, hw));
        *(uint2*)(smem + SA1 + sw) = make_uint2(pack_bf16x2(lx, ly), pack_bf16x2(lz, lw));
    }
}
// stage pre-split weights (hi/lo, [n][k]) into SB
__device__ __forceinline__ void stage_W(char* smem, const __nv_bfloat16* __restrict__ Wh,
                                        const __nv_bfloat16* __restrict__ Wl, int tid) {
    const uint2* H = (const uint2*)Wh;
    const uint2* L = (const uint2*)Wl;
    for (int i = tid; i < 4096; i += 256) {
        int n = i >> 5, k = (i & 31) << 2;
        uint32_t sw = tile_off(n, k);
        *(uint2*)(smem + SB0 + sw) = H[i];
        *(uint2*)(smem + SB1 + sw) = L[i];
    }
}
// 3-pass split HMMA over staged tiles -> acc[2][8][4]
__device__ __forceinline__ void mma_tile_all(uint32_t sb, int wid, int lid,
                                             float acc[2][8][4]) {
    const int m0w = (wid >> 1) * 32;
    const int n0w = (wid & 1) * 64;
    const int arow = m0w + (lid & 7) + ((lid >> 3) & 1) * 8;
    const int akad = (lid >> 4) * 8;
    const int brow0 = n0w + (lid & 7) + (lid >> 4) * 8;
    const int bkad = ((lid >> 3) & 1) * 8;
#pragma unroll
    for (int mf = 0; mf < 2; mf++)
#pragma unroll
        for (int nf = 0; nf < 8; nf++)
#pragma unroll
            for (int j = 0; j < 4; j++) acc[mf][nf][j] = 0.f;
    const uint32_t abase[3] = {sb + SA0, sb + SA0, sb + SA1};
    const uint32_t bbase[3] = {sb + SB0, sb + SB1, sb + SB0};
#pragma unroll
    for (int p = 0; p < 3; p++) {
        const uint32_t ab = abase[p], bb = bbase[p];
#pragma unroll
        for (int k0 = 0; k0 < 128; k0 += 16) {
            uint32_t a[2][4], b[4][4];
            ldsm4(a[0], frag_addr(ab, arow,      k0 + akad));
            ldsm4(a[1], frag_addr(ab, arow + 16, k0 + akad));
#pragma unroll
            for (int q = 0; q < 4; q++)
                ldsm4(b[q], frag_addr(bb, brow0 + q * 16, k0 + bkad));
#pragma unroll
            for (int mf = 0; mf < 2; mf++)
#pragma unroll
                for (int nf = 0; nf < 8; nf++)
                    mma16816(acc[mf][nf], a[mf], &b[nf >> 1][(nf & 1) * 2]);
        }
    }
}

// ---------------- weight combine: Wc = W_emb @ W_gcn, bc = b_emb @ W_gcn ----------------
__global__ void __launch_bounds__(256) k_combine(const float* __restrict__ We,
                                                 const float* __restrict__ Wg,
                                                 const float* __restrict__ be,
                                                 float* __restrict__ Wc,
                                                 float* __restrict__ bc) {
    const int col = threadIdx.x & 127;
    const int rr  = threadIdx.x >> 7;
    for (int p = 0; p < 4; p++) {
        int row = blockIdx.x * 8 + p * 2 + rr;
        float s = 0.f;
#pragma unroll 8
        for (int k = 0; k < 128; k++) s += We[row * 128 + k] * Wg[k * 128 + col];
        Wc[row * 128 + col] = s;
    }
    if (blockIdx.x == 0 && threadIdx.x < 128) {
        float s = 0.f;
        for (int k = 0; k < 128; k++) s += be[k] * Wg[k * 128 + col];
        bc[col] = s;
    }
}

// ---------------- weight prep: transpose + bf16 hi/lo split (6 slots) ----------------
__global__ void __launch_bounds__(128) k_split(
    const float* W0, const float* W1, const float* W2, const float* W3,
    const float* W4, const float* W5,
    __nv_bfloat16* wt0, __nv_bfloat16* wt1)
{
    extern __shared__ float s[];
    const float* Ws[6] = {W0, W1, W2, W3, W4, W5};
    const float* W = Ws[blockIdx.x];
    for (int i = threadIdx.x; i < 16384; i += 128) s[i] = W[i];
    __syncthreads();
    const int n = threadIdx.x;
    uint32_t* o0 = (uint32_t*)(wt0 + (size_t)blockIdx.x * 16384 + n * 128);
    uint32_t* o1 = (uint32_t*)(wt1 + (size_t)blockIdx.x * 16384 + n * 128);
    for (int k = 0; k < 128; k += 2) {
        float v0 = s[k * 128 + n], v1 = s[(k + 1) * 128 + n];
        __nv_bfloat16 h0 = __float2bfloat16(v0), h1 = __float2bfloat16(v1);
        __nv_bfloat16 l0 = __float2bfloat16(v0 - __bfloat162float(h0));
        __nv_bfloat16 l1 = __float2bfloat16(v1 - __bfloat162float(h1));
        o0[k >> 1] = pack_bf16x2(h0, h1);
        o1[k >> 1] = pack_bf16x2(l0, l1);
    }
}

// ---------------- single GEMM: C[M,128] = [relu](A @ W + b) ----------------
// MEANV: A row g is mean over v of vn2[g*32+v][*]
template<int RELU, int BIAS, int MEANV>
__global__ void __launch_bounds__(256) k_mma_gemm(
    const float* __restrict__ A,
    const __nv_bfloat16* __restrict__ Wt0,
    const __nv_bfloat16* __restrict__ Wt1,
    const float* __restrict__ bias,
    float* __restrict__ C)
{
    extern __shared__ char smem[];
    const uint32_t sb = smem_u32(smem);
    const int tid = threadIdx.x, wid = tid >> 5, lid = tid & 31;
    const int row0 = blockIdx.x * 128;

    if (MEANV) {
        for (int i = tid; i < 4096; i += 256) {
            int r = i >> 5, kq = i & 31;
            const float4* src = (const float4*)A + (size_t)(row0 + r) * VV * 32 + kq;
            float4 a = make_float4(0.f, 0.f, 0.f, 0.f);
#pragma unroll 8
            for (int v = 0; v < VV; v++) {
                float4 t = src[v * 32];
                a.x += t.x; a.y += t.y; a.z += t.z; a.w += t.w;
            }
            a.x *= (1.f/32.f); a.y *= (1.f/32.f); a.z *= (1.f/32.f); a.w *= (1.f/32.f);
            __nv_bfloat16 hx = __float2bfloat16(a.x), hy = __float2bfloat16(a.y);
            __nv_bfloat16 hz = __float2bfloat16(a.z), hw = __float2bfloat16(a.w);
            __nv_bfloat16 lx = __float2bfloat16(a.x - __bfloat162float(hx));
            __nv_bfloat16 ly = __float2bfloat16(a.y - __bfloat162float(hy));
            __nv_bfloat16 lz = __float2bfloat16(a.z - __bfloat162float(hz));
            __nv_bfloat16 lw = __float2bfloat16(a.w - __bfloat162float(hw));
            uint32_t sw = tile_off(r, (i & 31) << 2);
            *(uint2*)(smem + SA0 + sw) = make_uint2(pack_bf16x2(hx, hy), pack_bf16x2(hz, hw));
            *(uint2*)(smem + SA1 + sw) = make_uint2(pack_bf16x2(lx, ly), pack_bf16x2(lz, lw));
        }
    } else {
        stage_A(smem, A, row0, tid);
    }
    stage_W(smem, Wt0, Wt1, tid);
    __syncthreads();

    float acc[2][8][4];
    mma_tile_all(sb, wid, lid, acc);

    const int m0w = (wid >> 1) * 32;
    const int n0w = (wid & 1) * 64;
    const int crow = lid >> 2;
    const int ccol = (lid & 3) * 2;
#pragma unroll
    for (int mf = 0; mf < 2; mf++) {
        int gr = row0 + m0w + mf * 16 + crow;
        float* C0 = C + (size_t)gr * 128;
#pragma unroll
        for (int nf = 0; nf < 8; nf++) {
            int cn = n0w + nf * 8 + ccol;
            float2 bv = make_float2(0.f, 0.f);
            if (BIAS) bv = *(const float2*)(bias + cn);
            float2 v0 = make_float2(acc[mf][nf][0] + bv.x, acc[mf][nf][1] + bv.y);
            float2 v1 = make_float2(acc[mf][nf][2] + bv.x, acc[mf][nf][3] + bv.y);
            if (RELU) {
                v0.x = fmaxf(v0.x, 0.f); v0.y = fmaxf(v0.y, 0.f);
                v1.x = fmaxf(v1.x, 0.f); v1.y = fmaxf(v1.y, 0.f);
            }
            *(float2*)(C0 + cn)           = v0;
            *(float2*)(C0 + 8 * 128 + cn) = v1;
        }
    }
}

// ---------------- fused 2-layer MLP: Out = (relu(A@W1+b1))@W2 + b2 ----------------
__global__ void __launch_bounds__(256) k_mlp2(
    const float* __restrict__ A,
    const __nv_bfloat16* __restrict__ W1h, const __nv_bfloat16* __restrict__ W1l,
    const float* __restrict__ b1,
    const __nv_bfloat16* __restrict__ W2h, const __nv_bfloat16* __restrict__ W2l,
    const float* __restrict__ b2,
    float* __restrict__ Out)
{
    extern __shared__ char smem[];
    const uint32_t sb = smem_u32(smem);
    const int tid = threadIdx.x, wid = tid >> 5, lid = tid & 31;
    const int row0 = blockIdx.x * 128;

    stage_A(smem, A, row0, tid);
    stage_W(smem, W1h, W1l, tid);
    __syncthreads();

    float acc[2][8][4];
    mma_tile_all(sb, wid, lid, acc);

    const int m0w = (wid >> 1) * 32;
    const int n0w = (wid & 1) * 64;
    const int crow = lid >> 2;
    const int ccol = (lid & 3) * 2;

    __syncthreads();   // all warps done reading SA/SB

    // t = relu(acc + b1) -> restage bf16 hi/lo into SA (swizzled)
#pragma unroll
    for (int mf = 0; mf < 2; mf++) {
        int r = m0w + mf * 16 + crow;
#pragma unroll
        for (int nf = 0; nf < 8; nf++) {
            int cn = n0w + nf * 8 + ccol;
            float2 bv = *(const float2*)(b1 + cn);
            float tx = fmaxf(acc[mf][nf][0] + bv.x, 0.f);
            float ty = fmaxf(acc[mf][nf][1] + bv.y, 0.f);
            float ux = fmaxf(acc[mf][nf][2] + bv.x, 0.f);
            float uy = fmaxf(acc[mf][nf][3] + bv.y, 0.f);
            __nv_bfloat16 htx = __float2bfloat16(tx), hty = __float2bfloat16(ty);
            __nv_bfloat16 hux = __float2bfloat16(ux), huy = __float2bfloat16(uy);
            uint32_t sw0 = tile_off(r, cn);
            uint32_t sw1 = tile_off(r + 8, cn);
            *(uint32_t*)(smem + SA0 + sw0) = pack_bf16x2(htx, hty);
            *(uint32_t*)(smem + SA0 + sw1) = pack_bf16x2(hux, huy);
            *(uint32_t*)(smem + SA1 + sw0) = pack_bf16x2(
                __float2bfloat16(tx - __bfloat162float(htx)),
                __float2bfloat16(ty - __bfloat162float(hty)));
            *(uint32_t*)(smem + SA1 + sw1) = pack_bf16x2(
                __float2bfloat16(ux - __bfloat162float(hux)),
                __float2bfloat16(uy - __bfloat162float(huy)));
        }
    }
    stage_W(smem, W2h, W2l, tid);
    __syncthreads();

    mma_tile_all(sb, wid, lid, acc);

#pragma unroll
    for (int mf = 0; mf < 2; mf++) {
        int gr = row0 + m0w + mf * 16 + crow;
        float* C0 = Out + (size_t)gr * 128;
#pragma unroll
        for (int nf = 0; nf < 8; nf++) {
            int cn = n0w + nf * 8 + ccol;
            float2 bv = *(const float2*)(b2 + cn);
            *(float2*)(C0 + cn) = make_float2(acc[mf][nf][0] + bv.x, acc[mf][nf][1] + bv.y);
            *(float2*)(C0 + 8 * 128 + cn) = make_float2(acc[mf][nf][2] + bv.x,
                                                        acc[mf][nf][3] + bv.y);
        }
    }
}

// ---------------- edge count matrix ----------------
__global__ void k_edges(const int* __restrict__ ei, int* __restrict__ cntm) {
    int e = blockIdx.x * blockDim.x + threadIdx.x;
    int s = ei[e];
    int d = ei[EE + e];
    if ((unsigned)s >= NN || (unsigned)d >= NN) return;
    int g = s >> 6;
    atomicAdd(&cntm[(g << 12) | ((s & 63) << 6) | (d & 63)], 1);
}

// ---------------- GCN aggregation: dense 64x64 per graph, deterministic ----------------
__global__ void __launch_bounds__(128) k_gcn(const float* __restrict__ hw,
                                             const float* __restrict__ b_gcn,
                                             const int* __restrict__ cntm,
                                             float* __restrict__ h2)
{
    __shared__ float cntf[NPG * 65];     // padded stride 65
    __shared__ float ssrc[NPG * HH];
    __shared__ float sinv[NPG];

    const int g = blockIdx.x, tid = threadIdx.x;
    const int nbase = g * NPG;
    const int* cg = cntm + ((size_t)g << 12);

    for (int i = tid; i < NPG * NPG; i += 128)
        cntf[(i >> 6) * 65 + (i & 63)] = (float)cg[i];
    __syncthreads();

    if (tid < NPG) {
        float deg = 0.f;
#pragma unroll 8
        for (int s = 0; s < NPG; s++) deg += cntf[s * 65 + tid];
        sinv[tid] = rsqrtf(deg + 1.f);
    }
    __syncthreads();

    const float4* hw4 = (const float4*)(hw + (size_t)nbase * HH);
    float4* ssrc4 = (float4*)ssrc;
    for (int i = tid; i < NPG * HH / 4; i += 128) {
        float iv = sinv[i >> 5];
        float4 t = hw4[i];
        t.x *= iv; t.y *= iv; t.z *= iv; t.w *= iv;
        ssrc4[i] = t;
    }
    __syncthreads();

    const float bg = b_gcn[tid];
    float* outg = h2 + (size_t)nbase * HH;
#pragma unroll
    for (int dc = 0; dc < 16; dc++) {
        float a0 = 0.f, a1 = 0.f, a2 = 0.f, a3 = 0.f;
#pragma unroll 4
        for (int s = 0; s < NPG; s++) {
            float v  = ssrc[s * HH + tid];
            float w0 = cntf[s * 65 + dc * 4 + 0];
            float w1 = cntf[s * 65 + dc * 4 + 1];
            float w2 = cntf[s * 65 + dc * 4 + 2];
            float w3 = cntf[s * 65 + dc * 4 + 3];
            a0 += w0 * v; a1 += w1 * v; a2 += w2 * v; a3 += w3 * v;
        }
        float accs[4] = {a0, a1, a2, a3};
#pragma unroll
        for (int j = 0; j < 4; j++) {
            int dd = dc * 4 + j;
            float val = sinv[dd] * (accs[j] + ssrc[dd * HH + tid]);
            outg[(size_t)dd * HH + tid] = fmaxf(val + bg, 0.f);
        }
    }
}

// ---------------- per-graph attention + weighted scatter pool ----------------
__global__ void __launch_bounds__(128) k_att(const float* __restrict__ h2,
                                             const float* __restrict__ aff,
                                             const float* __restrict__ vemb,
                                             const float* __restrict__ eweights,
                                             float* __restrict__ vn_out)
{
    extern __shared__ float sm[];
    float* hgs   = sm;
    float* affs  = sm + NPG*HH;
    float* vembT = sm + 2*NPG*HH;
    float* sew   = vembT + HH*33;

    const int g = blockIdx.x, tid = threadIdx.x;

    const float4* hg4 = (const float4*)(h2  + (size_t)g*NPG*HH);
    const float4* af4 = (const float4*)(aff + (size_t)g*NPG*HH);
    float4* hgs4  = (float4*)hgs;
    float4* affs4 = (float4*)affs;
    for (int i = tid; i < NPG*HH/4; i += 128) { hgs4[i] = hg4[i]; affs4[i] = af4[i]; }

    const float* vg = vemb + (size_t)g*VV*HH;
    for (int i = tid; i < VV*HH; i += 128) {
        int v = i >> 7, k = i & 127;
        vembT[k*33 + v] = vg[i];
    }
    __syncthreads();

    const int v  = tid & 31;
    const int ng = tid >> 5;
    const float* ew_g = eweights + (size_t)g*NPG*VV;
    const float scale = 0.08838834764831845f;

    for (int c = 0; c < 4; c++) {
        int n0 = ng*16 + c*4;
        float acc0 = 0.f, acc1 = 0.f, acc2 = 0.f, acc3 = 0.f;
#pragma unroll 4
        for (int kq = 0; kq < 32; kq++) {
            float4 a0 = affs4[(n0+0)*32 + kq];
            float4 a1 = affs4[(n0+1)*32 + kq];
            float4 a2 = affs4[(n0+2)*32 + kq];
            float4 a3 = affs4[(n0+3)*32 + kq];
            float w0 = vembT[(kq*4+0)*33 + v];
            float w1 = vembT[(kq*4+1)*33 + v];
            float w2 = vembT[(kq*4+2)*33 + v];
            float w3 = vembT[(kq*4+3)*33 + v];
            acc0 += a0.x*w0 + a0.y*w1 + a0.z*w2 + a0.w*w3;
            acc1 += a1.x*w0 + a1.y*w1 + a1.z*w2 + a1.w*w3;
            acc2 += a2.x*w0 + a2.y*w1 + a2.z*w2 + a2.w*w3;
            acc3 += a3.x*w0 + a3.y*w1 + a3.z*w2 + a3.w*w3;
        }
        float accs[4] = {acc0, acc1, acc2, acc3};
#pragma unroll
        for (int j = 0; j < 4; j++) {
            int n = n0 + j;
            float att = accs[j] * scale;
            float sg = 1.f / (1.f + expf(-att));
            sew[n*32 + v] = ew_g[n*32 + v] * (1.f + sg);
        }
    }
    __syncthreads();

    if (tid < NPG) {
        float rs = 0.f;
        for (int v2 = 0; v2 < VV; v2++) rs += sew[tid*32 + v2];
        float denom = (rs == 0.f) ? 1.f : rs;
        float ivr = 1.f / denom;
        for (int v2 = 0; v2 < VV; v2++) sew[tid*32 + v2] *= ivr;
    }
    __syncthreads();

    const int c4  = tid & 31;
    const int vgp = tid >> 5;
    for (int vt = 0; vt < 2; vt++) {
        int vb = vgp*8 + vt*4;
        float4 acc[4];
#pragma unroll
        for (int u = 0; u < 4; u++) acc[u] = make_float4(0.f, 0.f, 0.f, 0.f);
        for (int n = 0; n < NPG; n++) {
            float4 hv = hgs4[n*32 + c4];
#pragma unroll
            for (int u = 0; u < 4; u++) {
                float w = sew[n*32 + vb + u];
                acc[u].x += w*hv.x; acc[u].y += w*hv.y;
                acc[u].z += w*hv.z; acc[u].w += w*hv.w;
            }
        }
#pragma unroll
        for (int u = 0; u < 4; u++)
            ((float4*)(vn_out + (size_t)(g*VV + vb + u)*HH))[c4] = acc[u];
    }
}

// ---------------- output head (128 -> 10) ----------------
__global__ void __launch_bounds__(128) k_head(const float* __restrict__ gf2,
                                              const float* __restrict__ W,
                                              const float* __restrict__ b,
                                              float* __restrict__ out) {
    __shared__ float row[HH];
    int g = blockIdx.x;
    row[threadIdx.x] = gf2[(size_t)g*HH + threadIdx.x];
    __syncthreads();
    if (threadIdx.x < NOUT) {
        float acc = b[threadIdx.x];
        for (int k = 0; k < HH; k++) acc += row[k] * W[k*NOUT + threadIdx.x];
        out[g*NOUT + threadIdx.x] = acc;
    }
}

// ---------------- launcher ----------------
extern "C" void kernel_launch(void* const* d_in, const int* in_sizes, int n_in,
                              void* d_out, int out_size)
{
    (void)in_sizes; (void)n_in; (void)out_size;
    const float* x        = (const float*)d_in[0];
    const int*   ei       = (const int*)d_in[1];
    const float* eweights = (const float*)d_in[3];
    const float* vemb     = (const float*)d_in[4];
    const float* W_emb  = (const float*)d_in[5];  const float* b_emb  = (const float*)d_in[6];
    const float* W_gcn  = (const float*)d_in[7];  const float* b_gcn  = (const float*)d_in[8];
    const float* aff_W1 = (const float*)d_in[9];  const float* aff_b1 = (const float*)d_in[10];
    const float* aff_W2 = (const float*)d_in[11]; const float* aff_b2 = (const float*)d_in[12];
    const float* vn_W1  = (const float*)d_in[13]; const float* vn_b1  = (const float*)d_in[14];
    const float* vn_W2  = (const float*)d_in[15]; const float* vn_b2  = (const float*)d_in[16];
    const float* mlp_W1 = (const float*)d_in[17]; const float* mlp_b1 = (const float*)d_in[18];
    const float* mlp_W2 = (const float*)d_in[19]; const float* mlp_b2 = (const float*)d_in[20];
    float* out = (float*)d_out;

    float *p_hw, *p_h2, *p_aff, *p_vn, *p_vn2, *p_gf2, *p_wc, *p_bc;
    int *p_cntm;
    __nv_bfloat16 *p_wt0, *p_wt1;
    cudaGetSymbolAddress((void**)&p_hw,   d_hw);
    cudaGetSymbolAddress((void**)&p_h2,   d_h2);
    cudaGetSymbolAddress((void**)&p_aff,  d_aff);
    cudaGetSymbolAddress((void**)&p_cntm, d_cntm);
    cudaGetSymbolAddress((void**)&p_vn,   d_vn);
    cudaGetSymbolAddress((void**)&p_vn2,  d_vn2);
    cudaGetSymbolAddress((void**)&p_gf2,  d_gf2);
    cudaGetSymbolAddress((void**)&p_wc,   d_wc);
    cudaGetSymbolAddress((void**)&p_bc,   d_bc);
    cudaGetSymbolAddress((void**)&p_wt0,  d_wt0);
    cudaGetSymbolAddress((void**)&p_wt1,  d_wt1);

    const int ATT_SMEM = (2*NPG*HH + HH*33 + NPG*VV) * (int)sizeof(float);
    cudaFuncSetAttribute(k_split,             cudaFuncAttributeMaxDynamicSharedMemorySize, 65536);
    cudaFuncSetAttribute(k_mma_gemm<0,1,0>,   cudaFuncAttributeMaxDynamicSharedMemorySize, GSM_TOTAL);
    cudaFuncSetAttribute(k_mma_gemm<1,1,1>,   cudaFuncAttributeMaxDynamicSharedMemorySize, GSM_TOTAL);
    cudaFuncSetAttribute(k_mlp2,              cudaFuncAttributeMaxDynamicSharedMemorySize, GSM_TOTAL);
    cudaFuncSetAttribute(k_att,               cudaFuncAttributeMaxDynamicSharedMemorySize, ATT_SMEM);

    #define WT0(i) (p_wt0 + (size_t)(i) * 16384)
    #define WT1(i) (p_wt1 + (size_t)(i) * 16384)

    // 0) combined weight + splits (slots: 0=Wc, 1=aff1, 2=aff2, 3=vn1, 4=vn2, 5=mlp1)
    k_combine<<<16, 256>>>(W_emb, W_gcn, b_emb, p_wc, p_bc);
    k_split<<<6, 128, 65536>>>(p_wc, aff_W1, aff_W2, vn_W1, vn_W2, mlp_W1, p_wt0, p_wt1);

    // 1) edge count matrix
    cudaMemsetAsync(p_cntm, 0, (size_t)GG * NPG * NPG * sizeof(int));
    k_edges<<<EE/256, 256>>>(ei, p_cntm);

    // 2) hw = x @ (W_emb@W_gcn) + b_emb@W_gcn   (h eliminated algebraically)
    k_mma_gemm<0,1,0><<<NN/128, 256, GSM_TOTAL>>>(x, WT0(0), WT1(0), p_bc, p_hw);

    // 3) GCN aggregation (dense per-graph) + relu
    k_gcn<<<GG, 128>>>(p_hw, b_gcn, p_cntm, p_h2);

    // 4) affinity MLP (fused 2-layer)
    k_mlp2<<<NN/128, 256, GSM_TOTAL>>>(p_h2, WT0(1), WT1(1), aff_b1,
                                       WT0(2), WT1(2), aff_b2, p_aff);

    // 5) attention vs virtual nodes + weighted pool
    k_att<<<GG, 128, ATT_SMEM>>>(p_h2, p_aff, vemb, eweights, p_vn);

    // 6) virtual-node MLP (fused 2-layer)
    k_mlp2<<<GG*VV/128, 256, GSM_TOTAL>>>(p_vn, WT0(3), WT1(3), vn_b1,
                                          WT0(4), WT1(4), vn_b2, p_vn2);

    // 7) gf = mean over V (fused into A-load) -> relu(gf@mlp_W1+b1) -> head
    k_mma_gemm<1,1,1><<<GG/128, 256, GSM_TOTAL>>>(p_vn2, WT0(5), WT1(5), mlp_b1, p_gf2);
    k_head<<<GG, 128>>>(p_gf2, mlp_W2, mlp_b2, out);
}

// round 6
// speedup vs baseline: 1.6311x; 1.3701x over previous
#include <cuda_runtime.h>
#include <cuda_bf16.h>
#include <math.h>
#include <stdint.h>

#define NN   65536
#define GG   1024
#define NPG  64
#define VV   32
#define HH   128
#define EE   1048576
#define NOUT 10

// ---------------- scratch (device globals; no allocation allowed) ----------------
__device__ float d_hw  [NN*HH];
__device__ float d_h2  [NN*HH];
__device__ float d_aff [NN*HH];
__device__ int   d_cntm[GG*NPG*NPG];
__device__ float d_vn  [GG*VV*HH];
__device__ float d_vn2 [GG*VV*HH];
__device__ float d_gf2 [GG*HH];
__device__ float d_wc  [HH*HH];
__device__ float d_bc  [HH];
__device__ __nv_bfloat16 d_wt0[6*HH*HH];
__device__ __nv_bfloat16 d_wt1[6*HH*HH];

// ================= helpers =================
__device__ __forceinline__ uint32_t smem_u32(const void* p) {
    uint32_t a;
    asm("{ .reg .u64 t; cvta.to.shared.u64 t, %1; cvt.u32.u64 %0, t; }" : "=r"(a) : "l"(p));
    return a;
}
__device__ __forceinline__ uint32_t pack_bf16x2(__nv_bfloat16 lo, __nv_bfloat16 hi) {
    return (uint32_t)__bfloat16_as_ushort(lo) | ((uint32_t)__bfloat16_as_ushort(hi) << 16);
}
__device__ __forceinline__ uint32_t tile_off(int r, int k) {
    uint32_t base = ((((uint32_t)k >> 6) * 16u + ((uint32_t)r >> 3)) << 10)
                  + (((uint32_t)r & 7) << 7) + (((uint32_t)k & 63) << 1);
    return base ^ ((base >> 3) & 0x70);
}
__device__ __forceinline__ uint32_t frag_addr(uint32_t base, int r, int k) {
    return base + (((uint32_t)k >> 6) << 14) + (((uint32_t)r >> 3) << 10)
         + (((uint32_t)r & 7) << 7) + ((((uint32_t)k & 63) << 1) ^ (((uint32_t)r & 7) << 4));
}
__device__ __forceinline__ void ldsm4(uint32_t* r, uint32_t addr) {
    asm volatile("ldmatrix.sync.aligned.m8n8.x4.shared.b16 {%0,%1,%2,%3}, [%4];"
        : "=r"(r[0]), "=r"(r[1]), "=r"(r[2]), "=r"(r[3]) : "r"(addr));
}
__device__ __forceinline__ void mma16816(float* c, const uint32_t* a, const uint32_t* b) {
    asm volatile("mma.sync.aligned.m16n8k16.row.col.f32.bf16.bf16.f32 "
        "{%0,%1,%2,%3}, {%4,%5,%6,%7}, {%8,%9}, {%0,%1,%2,%3};"
        : "+f"(c[0]), "+f"(c[1]), "+f"(c[2]), "+f"(c[3])
        : "r"(a[0]), "r"(a[1]), "r"(a[2]), "r"(a[3]), "r"(b[0]), "r"(b[1]));
}

#define SA0 0
#define SA1 32768
#define SB0 65536
#define SB1 98304
#define GSM_TOTAL 131072
#define NT 512

// stage fp32 A tile (128x128) -> bf16 hi/lo split, swizzled
__device__ __forceinline__ void stage_A(char* smem, const float* __restrict__ A,
                                        int row0, int tid) {
    const float4* A4 = (const float4*)(A + (size_t)row0 * 128);
#pragma unroll
    for (int i = tid; i < 4096; i += NT) {
        int r = i >> 5, k = (i & 31) << 2;
        float4 a = A4[i];
        __nv_bfloat16 hx = __float2bfloat16(a.x), hy = __float2bfloat16(a.y);
        __nv_bfloat16 hz = __float2bfloat16(a.z), hw = __float2bfloat16(a.w);
        __nv_bfloat16 lx = __float2bfloat16(a.x - __bfloat162float(hx));
        __nv_bfloat16 ly = __float2bfloat16(a.y - __bfloat162float(hy));
        __nv_bfloat16 lz = __float2bfloat16(a.z - __bfloat162float(hz));
        __nv_bfloat16 lw = __float2bfloat16(a.w - __bfloat162float(hw));
        uint32_t sw = tile_off(r, k);
        *(uint2*)(smem + SA0 + sw) = make_uint2(pack_bf16x2(hx, hy), pack_bf16x2(hz, hw));
        *(uint2*)(smem + SA1 + sw) = make_uint2(pack_bf16x2(lx, ly), pack_bf16x2(lz, lw));
    }
}
__device__ __forceinline__ void stage_W(char* smem, const __nv_bfloat16* __restrict__ Wh,
                                        const __nv_bfloat16* __restrict__ Wl, int tid) {
    const uint2* H = (const uint2*)Wh;
    const uint2* L = (const uint2*)Wl;
#pragma unroll
    for (int i = tid; i < 4096; i += NT) {
        int n = i >> 5, k = (i & 31) << 2;
        uint32_t sw = tile_off(n, k);
        *(uint2*)(smem + SB0 + sw) = H[i];
        *(uint2*)(smem + SB1 + sw) = L[i];
    }
}
// 16-warp 3-pass split HMMA: warp grid 4(M) x 4(N), warp tile 32x32 -> acc[2][4][4]
__device__ __forceinline__ void mma_tile_all(uint32_t sb, int wid, int lid,
                                             float acc[2][4][4]) {
    const int m0w = (wid >> 2) * 32;
    const int n0w = (wid & 3) * 32;
    const int arow = m0w + (lid & 7) + ((lid >> 3) & 1) * 8;
    const int akad = (lid >> 4) * 8;
    const int brow0 = n0w + (lid & 7) + (lid >> 4) * 8;
    const int bkad = ((lid >> 3) & 1) * 8;
#pragma unroll
    for (int mf = 0; mf < 2; mf++)
#pragma unroll
        for (int nf = 0; nf < 4; nf++)
#pragma unroll
            for (int j = 0; j < 4; j++) acc[mf][nf][j] = 0.f;
    const uint32_t abase[3] = {sb + SA0, sb + SA0, sb + SA1};
    const uint32_t bbase[3] = {sb + SB0, sb + SB1, sb + SB0};
#pragma unroll
    for (int p = 0; p < 3; p++) {
        const uint32_t ab = abase[p], bb = bbase[p];
#pragma unroll
        for (int k0 = 0; k0 < 128; k0 += 16) {
            uint32_t a[2][4], b[2][4];
            ldsm4(a[0], frag_addr(ab, arow,      k0 + akad));
            ldsm4(a[1], frag_addr(ab, arow + 16, k0 + akad));
            ldsm4(b[0], frag_addr(bb, brow0,      k0 + bkad));
            ldsm4(b[1], frag_addr(bb, brow0 + 16, k0 + bkad));
#pragma unroll
            for (int mf = 0; mf < 2; mf++)
#pragma unroll
                for (int nf = 0; nf < 4; nf++)
                    mma16816(acc[mf][nf], a[mf], &b[nf >> 1][(nf & 1) * 2]);
        }
    }
}

// ---------------- weight combine: Wc = W_emb @ W_gcn, bc = b_emb @ W_gcn ----------------
__global__ void __launch_bounds__(256) k_combine(const float* __restrict__ We,
                                                 const float* __restrict__ Wg,
                                                 const float* __restrict__ be,
                                                 float* __restrict__ Wc,
                                                 float* __restrict__ bc) {
    const int col = threadIdx.x & 127;
    const int rr  = threadIdx.x >> 7;
    for (int p = 0; p < 4; p++) {
        int row = blockIdx.x * 8 + p * 2 + rr;
        float s = 0.f;
#pragma unroll 8
        for (int k = 0; k < 128; k++) s += We[row * 128 + k] * Wg[k * 128 + col];
        Wc[row * 128 + col] = s;
    }
    if (blockIdx.x == 0 && threadIdx.x < 128) {
        float s = 0.f;
        for (int k = 0; k < 128; k++) s += be[k] * Wg[k * 128 + col];
        bc[col] = s;
    }
}

// ---------------- weight prep: transpose + bf16 hi/lo split ----------------
__global__ void __launch_bounds__(128) k_split(
    const float* W0, const float* W1, const float* W2, const float* W3,
    const float* W4, const float* W5,
    __nv_bfloat16* wt0, __nv_bfloat16* wt1)
{
    extern __shared__ float s[];
    const float* Ws[6] = {W0, W1, W2, W3, W4, W5};
    const float* W = Ws[blockIdx.x];
    for (int i = threadIdx.x; i < 16384; i += 128) s[i] = W[i];
    __syncthreads();
    const int n = threadIdx.x;
    uint32_t* o0 = (uint32_t*)(wt0 + (size_t)blockIdx.x * 16384 + n * 128);
    uint32_t* o1 = (uint32_t*)(wt1 + (size_t)blockIdx.x * 16384 + n * 128);
    for (int k = 0; k < 128; k += 2) {
        float v0 = s[k * 128 + n], v1 = s[(k + 1) * 128 + n];
        __nv_bfloat16 h0 = __float2bfloat16(v0), h1 = __float2bfloat16(v1);
        __nv_bfloat16 l0 = __float2bfloat16(v0 - __bfloat162float(h0));
        __nv_bfloat16 l1 = __float2bfloat16(v1 - __bfloat162float(h1));
        o0[k >> 1] = pack_bf16x2(h0, h1);
        o1[k >> 1] = pack_bf16x2(l0, l1);
    }
}

// ---------------- single GEMM: C[M,128] = [relu](A @ W + b) ----------------
template<int RELU, int BIAS, int MEANV>
__global__ void __launch_bounds__(NT) k_mma_gemm(
    const float* __restrict__ A,
    const __nv_bfloat16* __restrict__ Wt0,
    const __nv_bfloat16* __restrict__ Wt1,
    const float* __restrict__ bias,
    float* __restrict__ C)
{
    extern __shared__ char smem[];
    const uint32_t sb = smem_u32(smem);
    const int tid = threadIdx.x, wid = tid >> 5, lid = tid & 31;
    const int row0 = blockIdx.x * 128;

    if (MEANV) {
        for (int i = tid; i < 4096; i += NT) {
            int r = i >> 5, kq = i & 31;
            const float4* src = (const float4*)A + (size_t)(row0 + r) * VV * 32 + kq;
            float4 a = make_float4(0.f, 0.f, 0.f, 0.f);
#pragma unroll 8
            for (int v = 0; v < VV; v++) {
                float4 t = src[v * 32];
                a.x += t.x; a.y += t.y; a.z += t.z; a.w += t.w;
            }
            a.x *= (1.f/32.f); a.y *= (1.f/32.f); a.z *= (1.f/32.f); a.w *= (1.f/32.f);
            __nv_bfloat16 hx = __float2bfloat16(a.x), hy = __float2bfloat16(a.y);
            __nv_bfloat16 hz = __float2bfloat16(a.z), hw = __float2bfloat16(a.w);
            __nv_bfloat16 lx = __float2bfloat16(a.x - __bfloat162float(hx));
            __nv_bfloat16 ly = __float2bfloat16(a.y - __bfloat162float(hy));
            __nv_bfloat16 lz = __float2bfloat16(a.z - __bfloat162float(hz));
            __nv_bfloat16 lw = __float2bfloat16(a.w - __bfloat162float(hw));
            uint32_t sw = tile_off(r, kq << 2);
            *(uint2*)(smem + SA0 + sw) = make_uint2(pack_bf16x2(hx, hy), pack_bf16x2(hz, hw));
            *(uint2*)(smem + SA1 + sw) = make_uint2(pack_bf16x2(lx, ly), pack_bf16x2(lz, lw));
        }
    } else {
        stage_A(smem, A, row0, tid);
    }
    stage_W(smem, Wt0, Wt1, tid);
    __syncthreads();

    float acc[2][4][4];
    mma_tile_all(sb, wid, lid, acc);

    const int m0w = (wid >> 2) * 32;
    const int n0w = (wid & 3) * 32;
    const int crow = lid >> 2;
    const int ccol = (lid & 3) * 2;
#pragma unroll
    for (int mf = 0; mf < 2; mf++) {
        int gr = row0 + m0w + mf * 16 + crow;
        float* C0 = C + (size_t)gr * 128;
#pragma unroll
        for (int nf = 0; nf < 4; nf++) {
            int cn = n0w + nf * 8 + ccol;
            float2 bv = make_float2(0.f, 0.f);
            if (BIAS) bv = *(const float2*)(bias + cn);
            float2 v0 = make_float2(acc[mf][nf][0] + bv.x, acc[mf][nf][1] + bv.y);
            float2 v1 = make_float2(acc[mf][nf][2] + bv.x, acc[mf][nf][3] + bv.y);
            if (RELU) {
                v0.x = fmaxf(v0.x, 0.f); v0.y = fmaxf(v0.y, 0.f);
                v1.x = fmaxf(v1.x, 0.f); v1.y = fmaxf(v1.y, 0.f);
            }
            *(float2*)(C0 + cn)           = v0;
            *(float2*)(C0 + 8 * 128 + cn) = v1;
        }
    }
}

// ---------------- fused 2-layer MLP: Out = (relu(A@W1+b1))@W2 + b2 ----------------
__global__ void __launch_bounds__(NT) k_mlp2(
    const float* __restrict__ A,
    const __nv_bfloat16* __restrict__ W1h, const __nv_bfloat16* __restrict__ W1l,
    const float* __restrict__ b1,
    const __nv_bfloat16* __restrict__ W2h, const __nv_bfloat16* __restrict__ W2l,
    const float* __restrict__ b2,
    float* __restrict__ Out)
{
    extern __shared__ char smem[];
    const uint32_t sb = smem_u32(smem);
    const int tid = threadIdx.x, wid = tid >> 5, lid = tid & 31;
    const int row0 = blockIdx.x * 128;

    stage_A(smem, A, row0, tid);
    stage_W(smem, W1h, W1l, tid);
    __syncthreads();

    float acc[2][4][4];
    mma_tile_all(sb, wid, lid, acc);

    const int m0w = (wid >> 2) * 32;
    const int n0w = (wid & 3) * 32;
    const int crow = lid >> 2;
    const int ccol = (lid & 3) * 2;

    __syncthreads();   // all warps done reading SA/SB

    // t = relu(acc + b1) -> restage bf16 hi/lo into SA (swizzled)
#pragma unroll
    for (int mf = 0; mf < 2; mf++) {
        int r = m0w + mf * 16 + crow;
#pragma unroll
        for (int nf = 0; nf < 4; nf++) {
            int cn = n0w + nf * 8 + ccol;
            float2 bv = *(const float2*)(b1 + cn);
            float tx = fmaxf(acc[mf][nf][0] + bv.x, 0.f);
            float ty = fmaxf(acc[mf][nf][1] + bv.y, 0.f);
            float ux = fmaxf(acc[mf][nf][2] + bv.x, 0.f);
            float uy = fmaxf(acc[mf][nf][3] + bv.y, 0.f);
            __nv_bfloat16 htx = __float2bfloat16(tx), hty = __float2bfloat16(ty);
            __nv_bfloat16 hux = __float2bfloat16(ux), huy = __float2bfloat16(uy);
            uint32_t sw0 = tile_off(r, cn);
            uint32_t sw1 = tile_off(r + 8, cn);
            *(uint32_t*)(smem + SA0 + sw0) = pack_bf16x2(htx, hty);
            *(uint32_t*)(smem + SA0 + sw1) = pack_bf16x2(hux, huy);
            *(uint32_t*)(smem + SA1 + sw0) = pack_bf16x2(
                __float2bfloat16(tx - __bfloat162float(htx)),
                __float2bfloat16(ty - __bfloat162float(hty)));
            *(uint32_t*)(smem + SA1 + sw1) = pack_bf16x2(
                __float2bfloat16(ux - __bfloat162float(hux)),
                __float2bfloat16(uy - __bfloat162float(huy)));
        }
    }
    stage_W(smem, W2h, W2l, tid);
    __syncthreads();

    mma_tile_all(sb, wid, lid, acc);

#pragma unroll
    for (int mf = 0; mf < 2; mf++) {
        int gr = row0 + m0w + mf * 16 + crow;
        float* C0 = Out + (size_t)gr * 128;
#pragma unroll
        for (int nf = 0; nf < 4; nf++) {
            int cn = n0w + nf * 8 + ccol;
            float2 bv = *(const float2*)(b2 + cn);
            *(float2*)(C0 + cn) = make_float2(acc[mf][nf][0] + bv.x, acc[mf][nf][1] + bv.y);
            *(float2*)(C0 + 8 * 128 + cn) = make_float2(acc[mf][nf][2] + bv.x,
                                                        acc[mf][nf][3] + bv.y);
        }
    }
}

// ---------------- edge count matrix ----------------
__global__ void k_edges(const int* __restrict__ ei, int* __restrict__ cntm) {
    int e = blockIdx.x * blockDim.x + threadIdx.x;
    int s = ei[e];
    int d = ei[EE + e];
    if ((unsigned)s >= NN || (unsigned)d >= NN) return;
    int g = s >> 6;
    atomicAdd(&cntm[(g << 12) | ((s & 63) << 6) | (d & 63)], 1);
}

// ---------------- GCN aggregation: dense 64x64 per graph, deterministic ----------------
__global__ void __launch_bounds__(128) k_gcn(const float* __restrict__ hw,
                                             const float* __restrict__ b_gcn,
                                             const int* __restrict__ cntm,
                                             float* __restrict__ h2)
{
    __shared__ float cntf[NPG * 65];
    __shared__ float ssrc[NPG * HH];
    __shared__ float sinv[NPG];

    const int g = blockIdx.x, tid = threadIdx.x;
    const int nbase = g * NPG;
    const int* cg = cntm + ((size_t)g << 12);

    for (int i = tid; i < NPG * NPG; i += 128)
        cntf[(i >> 6) * 65 + (i & 63)] = (float)cg[i];
    __syncthreads();

    if (tid < NPG) {
        float deg = 0.f;
#pragma unroll 8
        for (int s = 0; s < NPG; s++) deg += cntf[s * 65 + tid];
        sinv[tid] = rsqrtf(deg + 1.f);
    }
    __syncthreads();

    const float4* hw4 = (const float4*)(hw + (size_t)nbase * HH);
    float4* ssrc4 = (float4*)ssrc;
    for (int i = tid; i < NPG * HH / 4; i += 128) {
        float iv = sinv[i >> 5];
        float4 t = hw4[i];
        t.x *= iv; t.y *= iv; t.z *= iv; t.w *= iv;
        ssrc4[i] = t;
    }
    __syncthreads();

    const float bg = b_gcn[tid];
    float* outg = h2 + (size_t)nbase * HH;
#pragma unroll
    for (int dc = 0; dc < 16; dc++) {
        float a0 = 0.f, a1 = 0.f, a2 = 0.f, a3 = 0.f;
#pragma unroll 4
        for (int s = 0; s < NPG; s++) {
            float v  = ssrc[s * HH + tid];
            float w0 = cntf[s * 65 + dc * 4 + 0];
            float w1 = cntf[s * 65 + dc * 4 + 1];
            float w2 = cntf[s * 65 + dc * 4 + 2];
            float w3 = cntf[s * 65 + dc * 4 + 3];
            a0 += w0 * v; a1 += w1 * v; a2 += w2 * v; a3 += w3 * v;
        }
        float accs[4] = {a0, a1, a2, a3};
#pragma unroll
        for (int j = 0; j < 4; j++) {
            int dd = dc * 4 + j;
            float val = sinv[dd] * (accs[j] + ssrc[dd * HH + tid]);
            outg[(size_t)dd * HH + tid] = fmaxf(val + bg, 0.f);
        }
    }
}

// ---------------- per-graph attention + weighted scatter pool (256 thr) ----------------
__global__ void __launch_bounds__(256) k_att(const float* __restrict__ h2,
                                             const float* __restrict__ aff,
                                             const float* __restrict__ vemb,
                                             const float* __restrict__ eweights,
                                             float* __restrict__ vn_out)
{
    extern __shared__ float sm[];
    float* hgs   = sm;
    float* affs  = sm + NPG*HH;
    float* vembT = sm + 2*NPG*HH;
    float* sew   = vembT + HH*33;

    const int g = blockIdx.x, tid = threadIdx.x;

    const float4* hg4 = (const float4*)(h2  + (size_t)g*NPG*HH);
    const float4* af4 = (const float4*)(aff + (size_t)g*NPG*HH);
    float4* hgs4  = (float4*)hgs;
    float4* affs4 = (float4*)affs;
    for (int i = tid; i < NPG*HH/4; i += 256) { hgs4[i] = hg4[i]; affs4[i] = af4[i]; }

    const float* vg = vemb + (size_t)g*VV*HH;
    for (int i = tid; i < VV*HH; i += 256) {
        int v = i >> 7, k = i & 127;
        vembT[k*33 + v] = vg[i];
    }
    __syncthreads();

    const int v  = tid & 31;
    const int ng = tid >> 5;      // 0..7
    const float* ew_g = eweights + (size_t)g*NPG*VV;
    const float scale = 0.08838834764831845f;

    for (int c = 0; c < 2; c++) {
        int n0 = ng*8 + c*4;
        float acc0 = 0.f, acc1 = 0.f, acc2 = 0.f, acc3 = 0.f;
#pragma unroll 4
        for (int kq = 0; kq < 32; kq++) {
            float4 a0 = affs4[(n0+0)*32 + kq];
            float4 a1 = affs4[(n0+1)*32 + kq];
            float4 a2 = affs4[(n0+2)*32 + kq];
            float4 a3 = affs4[(n0+3)*32 + kq];
            float w0 = vembT[(kq*4+0)*33 + v];
            float w1 = vembT[(kq*4+1)*33 + v];
            float w2 = vembT[(kq*4+2)*33 + v];
            float w3 = vembT[(kq*4+3)*33 + v];
            acc0 += a0.x*w0 + a0.y*w1 + a0.z*w2 + a0.w*w3;
            acc1 += a1.x*w0 + a1.y*w1 + a1.z*w2 + a1.w*w3;
            acc2 += a2.x*w0 + a2.y*w1 + a2.z*w2 + a2.w*w3;
            acc3 += a3.x*w0 + a3.y*w1 + a3.z*w2 + a3.w*w3;
        }
        float accs[4] = {acc0, acc1, acc2, acc3};
#pragma unroll
        for (int j = 0; j < 4; j++) {
            int n = n0 + j;
            float att = accs[j] * scale;
            float sg = 1.f / (1.f + expf(-att));
            sew[n*32 + v] = ew_g[n*32 + v] * (1.f + sg);
        }
    }
    __syncthreads();

    if (tid < NPG) {
        float rs = 0.f;
        for (int v2 = 0; v2 < VV; v2++) rs += sew[tid*32 + v2];
        float denom = (rs == 0.f) ? 1.f : rs;
        float ivr = 1.f / denom;
        for (int v2 = 0; v2 < VV; v2++) sew[tid*32 + v2] *= ivr;
    }
    __syncthreads();

    const int c4  = tid & 31;
    const int vgp = tid >> 5;     // 0..7 -> 4 v's each
    {
        int vb = vgp*4;
        float4 acc[4];
#pragma unroll
        for (int u = 0; u < 4; u++) acc[u] = make_float4(0.f, 0.f, 0.f, 0.f);
        for (int n = 0; n < NPG; n++) {
            float4 hv = hgs4[n*32 + c4];
#pragma unroll
            for (int u = 0; u < 4; u++) {
                float w = sew[n*32 + vb + u];
                acc[u].x += w*hv.x; acc[u].y += w*hv.y;
                acc[u].z += w*hv.z; acc[u].w += w*hv.w;
            }
        }
#pragma unroll
        for (int u = 0; u < 4; u++)
            ((float4*)(vn_out + (size_t)(g*VV + vb + u)*HH))[c4] = acc[u];
    }
}

// ---------------- output head (128 -> 10) ----------------
__global__ void __launch_bounds__(128) k_head(const float* __restrict__ gf2,
                                              const float* __restrict__ W,
                                              const float* __restrict__ b,
                                              float* __restrict__ out) {
    __shared__ float row[HH];
    int g = blockIdx.x;
    row[threadIdx.x] = gf2[(size_t)g*HH + threadIdx.x];
    __syncthreads();
    if (threadIdx.x < NOUT) {
        float acc = b[threadIdx.x];
        for (int k = 0; k < HH; k++) acc += row[k] * W[k*NOUT + threadIdx.x];
        out[g*NOUT + threadIdx.x] = acc;
    }
}

// ---------------- launcher ----------------
extern "C" void kernel_launch(void* const* d_in, const int* in_sizes, int n_in,
                              void* d_out, int out_size)
{
    (void)in_sizes; (void)n_in; (void)out_size;
    const float* x        = (const float*)d_in[0];
    const int*   ei       = (const int*)d_in[1];
    const float* eweights = (const float*)d_in[3];
    const float* vemb     = (const float*)d_in[4];
    const float* W_emb  = (const float*)d_in[5];  const float* b_emb  = (const float*)d_in[6];
    const float* W_gcn  = (const float*)d_in[7];  const float* b_gcn  = (const float*)d_in[8];
    const float* aff_W1 = (const float*)d_in[9];  const float* aff_b1 = (const float*)d_in[10];
    const float* aff_W2 = (const float*)d_in[11]; const float* aff_b2 = (const float*)d_in[12];
    const float* vn_W1  = (const float*)d_in[13]; const float* vn_b1  = (const float*)d_in[14];
    const float* vn_W2  = (const float*)d_in[15]; const float* vn_b2  = (const float*)d_in[16];
    const float* mlp_W1 = (const float*)d_in[17]; const float* mlp_b1 = (const float*)d_in[18];
    const float* mlp_W2 = (const float*)d_in[19]; const float* mlp_b2 = (const float*)d_in[20];
    float* out = (float*)d_out;

    float *p_hw, *p_h2, *p_aff, *p_vn, *p_vn2, *p_gf2, *p_wc, *p_bc;
    int *p_cntm;
    __nv_bfloat16 *p_wt0, *p_wt1;
    cudaGetSymbolAddress((void**)&p_hw,   d_hw);
    cudaGetSymbolAddress((void**)&p_h2,   d_h2);
    cudaGetSymbolAddress((void**)&p_aff,  d_aff);
    cudaGetSymbolAddress((void**)&p_cntm, d_cntm);
    cudaGetSymbolAddress((void**)&p_vn,   d_vn);
    cudaGetSymbolAddress((void**)&p_vn2,  d_vn2);
    cudaGetSymbolAddress((void**)&p_gf2,  d_gf2);
    cudaGetSymbolAddress((void**)&p_wc,   d_wc);
    cudaGetSymbolAddress((void**)&p_bc,   d_bc);
    cudaGetSymbolAddress((void**)&p_wt0,  d_wt0);
    cudaGetSymbolAddress((void**)&p_wt1,  d_wt1);

    const int ATT_SMEM = (2*NPG*HH + HH*33 + NPG*VV) * (int)sizeof(float);
    cudaFuncSetAttribute(k_split,           cudaFuncAttributeMaxDynamicSharedMemorySize, 65536);
    cudaFuncSetAttribute(k_mma_gemm<0,1,0>, cudaFuncAttributeMaxDynamicSharedMemorySize, GSM_TOTAL);
    cudaFuncSetAttribute(k_mma_gemm<1,1,1>, cudaFuncAttributeMaxDynamicSharedMemorySize, GSM_TOTAL);
    cudaFuncSetAttribute(k_mlp2,            cudaFuncAttributeMaxDynamicSharedMemorySize, GSM_TOTAL);
    cudaFuncSetAttribute(k_att,             cudaFuncAttributeMaxDynamicSharedMemorySize, ATT_SMEM);

    #define WT0(i) (p_wt0 + (size_t)(i) * 16384)
    #define WT1(i) (p_wt1 + (size_t)(i) * 16384)

    // 0) combined weight + splits (slots: 0=Wc, 1=aff1, 2=aff2, 3=vn1, 4=vn2, 5=mlp1)
    k_combine<<<16, 256>>>(W_emb, W_gcn, b_emb, p_wc, p_bc);
    k_split<<<6, 128, 65536>>>(p_wc, aff_W1, aff_W2, vn_W1, vn_W2, mlp_W1, p_wt0, p_wt1);

    // 1) edge count matrix
    cudaMemsetAsync(p_cntm, 0, (size_t)GG * NPG * NPG * sizeof(int));
    k_edges<<<EE/256, 256>>>(ei, p_cntm);

    // 2) hw = x @ (W_emb@W_gcn) + b_emb@W_gcn
    k_mma_gemm<0,1,0><<<NN/128, NT, GSM_TOTAL>>>(x, WT0(0), WT1(0), p_bc, p_hw);

    // 3) GCN aggregation (dense per-graph) + relu
    k_gcn<<<GG, 128>>>(p_hw, b_gcn, p_cntm, p_h2);

    // 4) affinity MLP (fused 2-layer)
    k_mlp2<<<NN/128, NT, GSM_TOTAL>>>(p_h2, WT0(1), WT1(1), aff_b1,
                                      WT0(2), WT1(2), aff_b2, p_aff);

    // 5) attention vs virtual nodes + weighted pool
    k_att<<<GG, 256, ATT_SMEM>>>(p_h2, p_aff, vemb, eweights, p_vn);

    // 6) virtual-node MLP (fused 2-layer)
    k_mlp2<<<GG*VV/128, NT, GSM_TOTAL>>>(p_vn, WT0(3), WT1(3), vn_b1,
                                         WT0(4), WT1(4), vn_b2, p_vn2);

    // 7) gf = mean over V (fused into A-load) -> relu(gf@mlp_W1+b1) -> head
    k_mma_gemm<1,1,1><<<GG/128, NT, GSM_TOTAL>>>(p_vn2, WT0(5), WT1(5), mlp_b1, p_gf2);
    k_head<<<GG, 128>>>(p_gf2, mlp_W2, mlp_b2, out);
}

// round 7
// speedup vs baseline: 1.6995x; 1.0419x over previous
#include <cuda_runtime.h>
#include <cuda_bf16.h>
#include <math.h>
#include <stdint.h>

#define NN   65536
#define GG   1024
#define NPG  64
#define VV   32
#define HH   128
#define EE   1048576
#define NOUT 10

// ---------------- scratch (device globals; no allocation allowed) ----------------
__device__ float d_h2  [NN*HH];
__device__ float d_aff [NN*HH];
__device__ int   d_cntm[GG*NPG*NPG];
__device__ float d_vn  [GG*VV*HH];
__device__ float d_vn2 [GG*VV*HH];
__device__ float d_gf2 [GG*HH];
__device__ float d_wc  [HH*HH];
__device__ float d_bc  [HH];
__device__ __nv_bfloat16 d_wt0[6*HH*HH];
__device__ __nv_bfloat16 d_wt1[6*HH*HH];

// ================= helpers =================
__device__ __forceinline__ uint32_t smem_u32(const void* p) {
    uint32_t a;
    asm("{ .reg .u64 t; cvta.to.shared.u64 t, %1; cvt.u32.u64 %0, t; }" : "=r"(a) : "l"(p));
    return a;
}
__device__ __forceinline__ uint32_t pack_bf16x2(__nv_bfloat16 lo, __nv_bfloat16 hi) {
    return (uint32_t)__bfloat16_as_ushort(lo) | ((uint32_t)__bfloat16_as_ushort(hi) << 16);
}
__device__ __forceinline__ uint32_t tile_off(int r, int k) {
    uint32_t base = ((((uint32_t)k >> 6) * 16u + ((uint32_t)r >> 3)) << 10)
                  + (((uint32_t)r & 7) << 7) + (((uint32_t)k & 63) << 1);
    return base ^ ((base >> 3) & 0x70);
}
__device__ __forceinline__ uint32_t frag_addr(uint32_t base, int r, int k) {
    return base + (((uint32_t)k >> 6) << 14) + (((uint32_t)r >> 3) << 10)
         + (((uint32_t)r & 7) << 7) + ((((uint32_t)k & 63) << 1) ^ (((uint32_t)r & 7) << 4));
}
__device__ __forceinline__ void ldsm4(uint32_t* r, uint32_t addr) {
    asm volatile("ldmatrix.sync.aligned.m8n8.x4.shared.b16 {%0,%1,%2,%3}, [%4];"
        : "=r"(r[0]), "=r"(r[1]), "=r"(r[2]), "=r"(r[3]) : "r"(addr));
}
__device__ __forceinline__ void mma16816(float* c, const uint32_t* a, const uint32_t* b) {
    asm volatile("mma.sync.aligned.m16n8k16.row.col.f32.bf16.bf16.f32 "
        "{%0,%1,%2,%3}, {%4,%5,%6,%7}, {%8,%9}, {%0,%1,%2,%3};"
        : "+f"(c[0]), "+f"(c[1]), "+f"(c[2]), "+f"(c[3])
        : "r"(a[0]), "r"(a[1]), "r"(a[2]), "r"(a[3]), "r"(b[0]), "r"(b[1]));
}

#define SA0 0
#define SA1 32768
#define SB0 65536
#define SB1 98304
#define GSM_TOTAL 131072
#define SC  131072
#define SINV 163840
#define XGCN_SMEM 164352
#define NT 512

// stage fp32 A tile (128x128) -> bf16 hi/lo split, swizzled
__device__ __forceinline__ void stage_A(char* smem, const float* __restrict__ A,
                                        int row0, int tid) {
    const float4* A4 = (const float4*)(A + (size_t)row0 * 128);
#pragma unroll
    for (int i = tid; i < 4096; i += NT) {
        int r = i >> 5, k = (i & 31) << 2;
        float4 a = A4[i];
        __nv_bfloat16 hx = __float2bfloat16(a.x), hy = __float2bfloat16(a.y);
        __nv_bfloat16 hz = __float2bfloat16(a.z), hw = __float2bfloat16(a.w);
        __nv_bfloat16 lx = __float2bfloat16(a.x - __bfloat162float(hx));
        __nv_bfloat16 ly = __float2bfloat16(a.y - __bfloat162float(hy));
        __nv_bfloat16 lz = __float2bfloat16(a.z - __bfloat162float(hz));
        __nv_bfloat16 lw = __float2bfloat16(a.w - __bfloat162float(hw));
        uint32_t sw = tile_off(r, k);
        *(uint2*)(smem + SA0 + sw) = make_uint2(pack_bf16x2(hx, hy), pack_bf16x2(hz, hw));
        *(uint2*)(smem + SA1 + sw) = make_uint2(pack_bf16x2(lx, ly), pack_bf16x2(lz, lw));
    }
}
__device__ __forceinline__ void stage_W(char* smem, const __nv_bfloat16* __restrict__ Wh,
                                        const __nv_bfloat16* __restrict__ Wl, int tid) {
    const uint2* H = (const uint2*)Wh;
    const uint2* L = (const uint2*)Wl;
#pragma unroll
    for (int i = tid; i < 4096; i += NT) {
        int n = i >> 5, k = (i & 31) << 2;
        uint32_t sw = tile_off(n, k);
        *(uint2*)(smem + SB0 + sw) = H[i];
        *(uint2*)(smem + SB1 + sw) = L[i];
    }
}
// NP-pass HMMA: warp grid 4(M) x 4(N), warp tile 32x32 -> acc[2][4][4]
template<int NP>
__device__ __forceinline__ void mma_passes(const uint32_t* al, const uint32_t* bl,
                                           int wid, int lid, float acc[2][4][4]) {
    const int m0w = (wid >> 2) * 32;
    const int n0w = (wid & 3) * 32;
    const int arow = m0w + (lid & 7) + ((lid >> 3) & 1) * 8;
    const int akad = (lid >> 4) * 8;
    const int brow0 = n0w + (lid & 7) + (lid >> 4) * 8;
    const int bkad = ((lid >> 3) & 1) * 8;
#pragma unroll
    for (int mf = 0; mf < 2; mf++)
#pragma unroll
        for (int nf = 0; nf < 4; nf++)
#pragma unroll
            for (int j = 0; j < 4; j++) acc[mf][nf][j] = 0.f;
#pragma unroll
    for (int p = 0; p < NP; p++) {
        const uint32_t ab = al[p], bb = bl[p];
#pragma unroll
        for (int k0 = 0; k0 < 128; k0 += 16) {
            uint32_t a[2][4], b[2][4];
            ldsm4(a[0], frag_addr(ab, arow,      k0 + akad));
            ldsm4(a[1], frag_addr(ab, arow + 16, k0 + akad));
            ldsm4(b[0], frag_addr(bb, brow0,      k0 + bkad));
            ldsm4(b[1], frag_addr(bb, brow0 + 16, k0 + bkad));
#pragma unroll
            for (int mf = 0; mf < 2; mf++)
#pragma unroll
                for (int nf = 0; nf < 4; nf++)
                    mma16816(acc[mf][nf], a[mf], &b[nf >> 1][(nf & 1) * 2]);
        }
    }
}

// ---------------- weight combine: Wc = W_emb @ W_gcn, bc = b_emb @ W_gcn ----------------
__global__ void __launch_bounds__(256) k_combine(const float* __restrict__ We,
                                                 const float* __restrict__ Wg,
                                                 const float* __restrict__ be,
                                                 float* __restrict__ Wc,
                                                 float* __restrict__ bc) {
    const int col = threadIdx.x & 127;
    const int rr  = threadIdx.x >> 7;
    for (int p = 0; p < 4; p++) {
        int row = blockIdx.x * 8 + p * 2 + rr;
        float s = 0.f;
#pragma unroll 8
        for (int k = 0; k < 128; k++) s += We[row * 128 + k] * Wg[k * 128 + col];
        Wc[row * 128 + col] = s;
    }
    if (blockIdx.x == 0 && threadIdx.x < 128) {
        float s = 0.f;
        for (int k = 0; k < 128; k++) s += be[k] * Wg[k * 128 + col];
        bc[col] = s;
    }
}

// ---------------- weight prep: transpose + bf16 hi/lo split ----------------
__global__ void __launch_bounds__(128) k_split(
    const float* W0, const float* W1, const float* W2, const float* W3,
    const float* W4, const float* W5,
    __nv_bfloat16* wt0, __nv_bfloat16* wt1)
{
    extern __shared__ float s[];
    const float* Ws[6] = {W0, W1, W2, W3, W4, W5};
    const float* W = Ws[blockIdx.x];
    for (int i = threadIdx.x; i < 16384; i += 128) s[i] = W[i];
    __syncthreads();
    const int n = threadIdx.x;
    uint32_t* o0 = (uint32_t*)(wt0 + (size_t)blockIdx.x * 16384 + n * 128);
    uint32_t* o1 = (uint32_t*)(wt1 + (size_t)blockIdx.x * 16384 + n * 128);
    for (int k = 0; k < 128; k += 2) {
        float v0 = s[k * 128 + n], v1 = s[(k + 1) * 128 + n];
        __nv_bfloat16 h0 = __float2bfloat16(v0), h1 = __float2bfloat16(v1);
        __nv_bfloat16 l0 = __float2bfloat16(v0 - __bfloat162float(h0));
        __nv_bfloat16 l1 = __float2bfloat16(v1 - __bfloat162float(h1));
        o0[k >> 1] = pack_bf16x2(h0, h1);
        o1[k >> 1] = pack_bf16x2(l0, l1);
    }
}

// ---------------- fused x-GEMM + GCN: h2 = relu(D^-1/2 (A+I) D^-1/2 (x@Wc+bc) + bg) ------
__global__ void __launch_bounds__(NT) k_xgcn(
    const float* __restrict__ x,
    const __nv_bfloat16* __restrict__ Wch, const __nv_bfloat16* __restrict__ Wcl,
    const float* __restrict__ bc, const float* __restrict__ b_gcn,
    const int* __restrict__ cntm,
    float* __restrict__ h2)
{
    extern __shared__ char smem[];
    const uint32_t sb = smem_u32(smem);
    const int tid = threadIdx.x, wid = tid >> 5, lid = tid & 31;
    const int row0 = blockIdx.x * 128;
    const int g0 = row0 >> 6;                     // first of 2 graphs
    const int* cg = cntm + ((size_t)g0 << 12);
    float* sinv = (float*)(smem + SINV);

    // zero cnt tile (off-diagonal blocks must be 0)
    for (int i = tid; i < 8192; i += NT) ((uint32_t*)(smem + SC))[i] = 0;

    // stage x and Wc while cnt zeroing settles
    stage_A(smem, x, row0, tid);
    stage_W(smem, Wch, Wcl, tid);
    __syncthreads();

    // fill block-diagonal cnt matrix: A[d][s] = cnt[s][d] (+1 on diag, self loop)
    for (int i = tid; i < 8192; i += NT) {
        int gl = i >> 12;
        int s = (i >> 6) & 63, d = i & 63;
        float v = (float)cg[(gl << 12) + (s << 6) + d] + (s == d ? 1.f : 0.f);
        *(__nv_bfloat16*)(smem + SC + tile_off(gl * 64 + d, gl * 64 + s)) = __float2bfloat16(v);
    }
    // deg/inv per destination node
    if (tid < 128) {
        int gl = tid >> 6, dl = tid & 63;
        const int* cgg = cg + (gl << 12);
        int deg = 0;
#pragma unroll 8
        for (int s = 0; s < 64; s++) deg += cgg[(s << 6) + dl];
        sinv[tid] = rsqrtf((float)deg + 1.f);
    }

    // phase 1: hw = x @ Wc (3-pass split)
    const uint32_t al1[3] = {sb + SA0, sb + SA0, sb + SA1};
    const uint32_t bl1[3] = {sb + SB0, sb + SB1, sb + SB0};
    float acc[2][4][4];
    mma_passes<3>(al1, bl1, wid, lid, acc);

    const int m0w = (wid >> 2) * 32;
    const int n0w = (wid & 3) * 32;
    const int crow = lid >> 2;
    const int ccol = (lid & 3) * 2;

    __syncthreads();   // everyone done reading SA/SB

    // restage ssrc^T = ((hw+bc)*inv[s])^T into SB0/SB1 (hi/lo), layout [h][s]
#pragma unroll
    for (int mf = 0; mf < 2; mf++) {
        int r = m0w + mf * 16 + crow;
        float iv0 = sinv[r], iv1 = sinv[r + 8];
#pragma unroll
        for (int nf = 0; nf < 4; nf++) {
            int cn = n0w + nf * 8 + ccol;
            float2 bv = *(const float2*)(bc + cn);
            float v00 = (acc[mf][nf][0] + bv.x) * iv0;
            float v01 = (acc[mf][nf][1] + bv.y) * iv0;
            float v10 = (acc[mf][nf][2] + bv.x) * iv1;
            float v11 = (acc[mf][nf][3] + bv.y) * iv1;
            __nv_bfloat16 h00 = __float2bfloat16(v00), h01 = __float2bfloat16(v01);
            __nv_bfloat16 h10 = __float2bfloat16(v10), h11 = __float2bfloat16(v11);
            // transposed positions: (row=h=cn, k=s=r)
            *(__nv_bfloat16*)(smem + SB0 + tile_off(cn,     r))     = h00;
            *(__nv_bfloat16*)(smem + SB0 + tile_off(cn + 1, r))     = h01;
            *(__nv_bfloat16*)(smem + SB0 + tile_off(cn,     r + 8)) = h10;
            *(__nv_bfloat16*)(smem + SB0 + tile_off(cn + 1, r + 8)) = h11;
            *(__nv_bfloat16*)(smem + SB1 + tile_off(cn,     r))     =
                __float2bfloat16(v00 - __bfloat162float(h00));
            *(__nv_bfloat16*)(smem + SB1 + tile_off(cn + 1, r))     =
                __float2bfloat16(v01 - __bfloat162float(h01));
            *(__nv_bfloat16*)(smem + SB1 + tile_off(cn,     r + 8)) =
                __float2bfloat16(v10 - __bfloat162float(h10));
            *(__nv_bfloat16*)(smem + SB1 + tile_off(cn + 1, r + 8)) =
                __float2bfloat16(v11 - __bfloat162float(h11));
        }
    }
    __syncthreads();

    // phase 2: agg = cnt_bd @ ssrc  (2-pass over ssrc hi/lo; cnt exact)
    const uint32_t al2[2] = {sb + SC, sb + SC};
    const uint32_t bl2[2] = {sb + SB0, sb + SB1};
    mma_passes<2>(al2, bl2, wid, lid, acc);

    // epilogue: h2 = relu(inv[d]*agg + b_gcn)
#pragma unroll
    for (int mf = 0; mf < 2; mf++) {
        int r = m0w + mf * 16 + crow;
        float iv0 = sinv[r], iv1 = sinv[r + 8];
        float* C0 = h2 + (size_t)(row0 + r) * 128;
#pragma unroll
        for (int nf = 0; nf < 4; nf++) {
            int cn = n0w + nf * 8 + ccol;
            float2 bg = *(const float2*)(b_gcn + cn);
            float2 v0 = make_float2(fmaxf(acc[mf][nf][0] * iv0 + bg.x, 0.f),
                                    fmaxf(acc[mf][nf][1] * iv0 + bg.y, 0.f));
            float2 v1 = make_float2(fmaxf(acc[mf][nf][2] * iv1 + bg.x, 0.f),
                                    fmaxf(acc[mf][nf][3] * iv1 + bg.y, 0.f));
            *(float2*)(C0 + cn)           = v0;
            *(float2*)(C0 + 8 * 128 + cn) = v1;
        }
    }
}

// ---------------- single GEMM: C[M,128] = [relu](A @ W + b) ----------------
template<int RELU, int BIAS, int MEANV>
__global__ void __launch_bounds__(NT) k_mma_gemm(
    const float* __restrict__ A,
    const __nv_bfloat16* __restrict__ Wt0,
    const __nv_bfloat16* __restrict__ Wt1,
    const float* __restrict__ bias,
    float* __restrict__ C)
{
    extern __shared__ char smem[];
    const uint32_t sb = smem_u32(smem);
    const int tid = threadIdx.x, wid = tid >> 5, lid = tid & 31;
    const int row0 = blockIdx.x * 128;

    if (MEANV) {
        for (int i = tid; i < 4096; i += NT) {
            int r = i >> 5, kq = i & 31;
            const float4* src = (const float4*)A + (size_t)(row0 + r) * VV * 32 + kq;
            float4 a = make_float4(0.f, 0.f, 0.f, 0.f);
#pragma unroll 8
            for (int v = 0; v < VV; v++) {
                float4 t = src[v * 32];
                a.x += t.x; a.y += t.y; a.z += t.z; a.w += t.w;
            }
            a.x *= (1.f/32.f); a.y *= (1.f/32.f); a.z *= (1.f/32.f); a.w *= (1.f/32.f);
            __nv_bfloat16 hx = __float2bfloat16(a.x), hy = __float2bfloat16(a.y);
            __nv_bfloat16 hz = __float2bfloat16(a.z), hw = __float2bfloat16(a.w);
            __nv_bfloat16 lx = __float2bfloat16(a.x - __bfloat162float(hx));
            __nv_bfloat16 ly = __float2bfloat16(a.y - __bfloat162float(hy));
            __nv_bfloat16 lz = __float2bfloat16(a.z - __bfloat162float(hz));
            __nv_bfloat16 lw = __float2bfloat16(a.w - __bfloat162float(hw));
            uint32_t sw = tile_off(r, kq << 2);
            *(uint2*)(smem + SA0 + sw) = make_uint2(pack_bf16x2(hx, hy), pack_bf16x2(hz, hw));
            *(uint2*)(smem + SA1 + sw) = make_uint2(pack_bf16x2(lx, ly), pack_bf16x2(lz, lw));
        }
    } else {
        stage_A(smem, A, row0, tid);
    }
    stage_W(smem, Wt0, Wt1, tid);
    __syncthreads();

    const uint32_t al[3] = {sb + SA0, sb + SA0, sb + SA1};
    const uint32_t bl[3] = {sb + SB0, sb + SB1, sb + SB0};
    float acc[2][4][4];
    mma_passes<3>(al, bl, wid, lid, acc);

    const int m0w = (wid >> 2) * 32;
    const int n0w = (wid & 3) * 32;
    const int crow = lid >> 2;
    const int ccol = (lid & 3) * 2;
#pragma unroll
    for (int mf = 0; mf < 2; mf++) {
        int gr = row0 + m0w + mf * 16 + crow;
        float* C0 = C + (size_t)gr * 128;
#pragma unroll
        for (int nf = 0; nf < 4; nf++) {
            int cn = n0w + nf * 8 + ccol;
            float2 bv = make_float2(0.f, 0.f);
            if (BIAS) bv = *(const float2*)(bias + cn);
            float2 v0 = make_float2(acc[mf][nf][0] + bv.x, acc[mf][nf][1] + bv.y);
            float2 v1 = make_float2(acc[mf][nf][2] + bv.x, acc[mf][nf][3] + bv.y);
            if (RELU) {
                v0.x = fmaxf(v0.x, 0.f); v0.y = fmaxf(v0.y, 0.f);
                v1.x = fmaxf(v1.x, 0.f); v1.y = fmaxf(v1.y, 0.f);
            }
            *(float2*)(C0 + cn)           = v0;
            *(float2*)(C0 + 8 * 128 + cn) = v1;
        }
    }
}

// ---------------- fused 2-layer MLP: Out = (relu(A@W1+b1))@W2 + b2 ----------------
__global__ void __launch_bounds__(NT) k_mlp2(
    const float* __restrict__ A,
    const __nv_bfloat16* __restrict__ W1h, const __nv_bfloat16* __restrict__ W1l,
    const float* __restrict__ b1,
    const __nv_bfloat16* __restrict__ W2h, const __nv_bfloat16* __restrict__ W2l,
    const float* __restrict__ b2,
    float* __restrict__ Out)
{
    extern __shared__ char smem[];
    const uint32_t sb = smem_u32(smem);
    const int tid = threadIdx.x, wid = tid >> 5, lid = tid & 31;
    const int row0 = blockIdx.x * 128;

    stage_A(smem, A, row0, tid);
    stage_W(smem, W1h, W1l, tid);
    __syncthreads();

    const uint32_t al[3] = {sb + SA0, sb + SA0, sb + SA1};
    const uint32_t bl[3] = {sb + SB0, sb + SB1, sb + SB0};
    float acc[2][4][4];
    mma_passes<3>(al, bl, wid, lid, acc);

    const int m0w = (wid >> 2) * 32;
    const int n0w = (wid & 3) * 32;
    const int crow = lid >> 2;
    const int ccol = (lid & 3) * 2;

    __syncthreads();

#pragma unroll
    for (int mf = 0; mf < 2; mf++) {
        int r = m0w + mf * 16 + crow;
#pragma unroll
        for (int nf = 0; nf < 4; nf++) {
            int cn = n0w + nf * 8 + ccol;
            float2 bv = *(const float2*)(b1 + cn);
            float tx = fmaxf(acc[mf][nf][0] + bv.x, 0.f);
            float ty = fmaxf(acc[mf][nf][1] + bv.y, 0.f);
            float ux = fmaxf(acc[mf][nf][2] + bv.x, 0.f);
            float uy = fmaxf(acc[mf][nf][3] + bv.y, 0.f);
            __nv_bfloat16 htx = __float2bfloat16(tx), hty = __float2bfloat16(ty);
            __nv_bfloat16 hux = __float2bfloat16(ux), huy = __float2bfloat16(uy);
            uint32_t sw0 = tile_off(r, cn);
            uint32_t sw1 = tile_off(r + 8, cn);
            *(uint32_t*)(smem + SA0 + sw0) = pack_bf16x2(htx, hty);
            *(uint32_t*)(smem + SA0 + sw1) = pack_bf16x2(hux, huy);
            *(uint32_t*)(smem + SA1 + sw0) = pack_bf16x2(
                __float2bfloat16(tx - __bfloat162float(htx)),
                __float2bfloat16(ty - __bfloat162float(hty)));
            *(uint32_t*)(smem + SA1 + sw1) = pack_bf16x2(
                __float2bfloat16(ux - __bfloat162float(hux)),
                __float2bfloat16(uy - __bfloat162float(huy)));
        }
    }
    stage_W(smem, W2h, W2l, tid);
    __syncthreads();

    mma_passes<3>(al, bl, wid, lid, acc);

#pragma unroll
    for (int mf = 0; mf < 2; mf++) {
        int gr = row0 + m0w + mf * 16 + crow;
        float* C0 = Out + (size_t)gr * 128;
#pragma unroll
        for (int nf = 0; nf < 4; nf++) {
            int cn = n0w + nf * 8 + ccol;
            float2 bv = *(const float2*)(b2 + cn);
            *(float2*)(C0 + cn) = make_float2(acc[mf][nf][0] + bv.x, acc[mf][nf][1] + bv.y);
            *(float2*)(C0 + 8 * 128 + cn) = make_float2(acc[mf][nf][2] + bv.x,
                                                        acc[mf][nf][3] + bv.y);
        }
    }
}

// ---------------- edge count matrix ----------------
__global__ void k_edges(const int* __restrict__ ei, int* __restrict__ cntm) {
    int e = blockIdx.x * blockDim.x + threadIdx.x;
    int s = ei[e];
    int d = ei[EE + e];
    if ((unsigned)s >= NN || (unsigned)d >= NN) return;
    int g = s >> 6;
    atomicAdd(&cntm[(g << 12) | ((s & 63) << 6) | (d & 63)], 1);
}

// ---------------- per-graph attention + weighted scatter pool (256 thr) ----------------
__global__ void __launch_bounds__(256) k_att(const float* __restrict__ h2,
                                             const float* __restrict__ aff,
                                             const float* __restrict__ vemb,
                                             const float* __restrict__ eweights,
                                             float* __restrict__ vn_out)
{
    extern __shared__ float sm[];
    float* hgs   = sm;
    float* affs  = sm + NPG*HH;
    float* vembT = sm + 2*NPG*HH;
    float* sew   = vembT + HH*33;

    const int g = blockIdx.x, tid = threadIdx.x;

    const float4* hg4 = (const float4*)(h2  + (size_t)g*NPG*HH);
    const float4* af4 = (const float4*)(aff + (size_t)g*NPG*HH);
    float4* hgs4  = (float4*)hgs;
    float4* affs4 = (float4*)affs;
    for (int i = tid; i < NPG*HH/4; i += 256) { hgs4[i] = hg4[i]; affs4[i] = af4[i]; }

    const float* vg = vemb + (size_t)g*VV*HH;
    for (int i = tid; i < VV*HH; i += 256) {
        int v = i >> 7, k = i & 127;
        vembT[k*33 + v] = vg[i];
    }
    __syncthreads();

    const int v  = tid & 31;
    const int ng = tid >> 5;
    const float* ew_g = eweights + (size_t)g*NPG*VV;
    const float scale = 0.08838834764831845f;

    for (int c = 0; c < 2; c++) {
        int n0 = ng*8 + c*4;
        float acc0 = 0.f, acc1 = 0.f, acc2 = 0.f, acc3 = 0.f;
#pragma unroll 4
        for (int kq = 0; kq < 32; kq++) {
            float4 a0 = affs4[(n0+0)*32 + kq];
            float4 a1 = affs4[(n0+1)*32 + kq];
            float4 a2 = affs4[(n0+2)*32 + kq];
            float4 a3 = affs4[(n0+3)*32 + kq];
            float w0 = vembT[(kq*4+0)*33 + v];
            float w1 = vembT[(kq*4+1)*33 + v];
            float w2 = vembT[(kq*4+2)*33 + v];
            float w3 = vembT[(kq*4+3)*33 + v];
            acc0 += a0.x*w0 + a0.y*w1 + a0.z*w2 + a0.w*w3;
            acc1 += a1.x*w0 + a1.y*w1 + a1.z*w2 + a1.w*w3;
            acc2 += a2.x*w0 + a2.y*w1 + a2.z*w2 + a2.w*w3;
            acc3 += a3.x*w0 + a3.y*w1 + a3.z*w2 + a3.w*w3;
        }
        float accs[4] = {acc0, acc1, acc2, acc3};
#pragma unroll
        for (int j = 0; j < 4; j++) {
            int n = n0 + j;
            float att = accs[j] * scale;
            float sg = 1.f / (1.f + expf(-att));
            sew[n*32 + v] = ew_g[n*32 + v] * (1.f + sg);
        }
    }
    __syncthreads();

    if (tid < NPG) {
        float rs = 0.f;
        for (int v2 = 0; v2 < VV; v2++) rs += sew[tid*32 + v2];
        float denom = (rs == 0.f) ? 1.f : rs;
        float ivr = 1.f / denom;
        for (int v2 = 0; v2 < VV; v2++) sew[tid*32 + v2] *= ivr;
    }
    __syncthreads();

    const int c4  = tid & 31;
    const int vgp = tid >> 5;
    {
        int vb = vgp*4;
        float4 acc[4];
#pragma unroll
        for (int u = 0; u < 4; u++) acc[u] = make_float4(0.f, 0.f, 0.f, 0.f);
        for (int n = 0; n < NPG; n++) {
            float4 hv = hgs4[n*32 + c4];
#pragma unroll
            for (int u = 0; u < 4; u++) {
                float w = sew[n*32 + vb + u];
                acc[u].x += w*hv.x; acc[u].y += w*hv.y;
                acc[u].z += w*hv.z; acc[u].w += w*hv.w;
            }
        }
#pragma unroll
        for (int u = 0; u < 4; u++)
            ((float4*)(vn_out + (size_t)(g*VV + vb + u)*HH))[c4] = acc[u];
    }
}

// ---------------- output head (128 -> 10) ----------------
__global__ void __launch_bounds__(128) k_head(const float* __restrict__ gf2,
                                              const float* __restrict__ W,
                                              const float* __restrict__ b,
                                              float* __restrict__ out) {
    __shared__ float row[HH];
    int g = blockIdx.x;
    row[threadIdx.x] = gf2[(size_t)g*HH + threadIdx.x];
    __syncthreads();
    if (threadIdx.x < NOUT) {
        float acc = b[threadIdx.x];
        for (int k = 0; k < HH; k++) acc += row[k] * W[k*NOUT + threadIdx.x];
        out[g*NOUT + threadIdx.x] = acc;
    }
}

// ---------------- launcher ----------------
extern "C" void kernel_launch(void* const* d_in, const int* in_sizes, int n_in,
                              void* d_out, int out_size)
{
    (void)in_sizes; (void)n_in; (void)out_size;
    const float* x        = (const float*)d_in[0];
    const int*   ei       = (const int*)d_in[1];
    const float* eweights = (const float*)d_in[3];
    const float* vemb     = (const float*)d_in[4];
    const float* W_emb  = (const float*)d_in[5];  const float* b_emb  = (const float*)d_in[6];
    const float* W_gcn  = (const float*)d_in[7];  const float* b_gcn  = (const float*)d_in[8];
    const float* aff_W1 = (const float*)d_in[9];  const float* aff_b1 = (const float*)d_in[10];
    const float* aff_W2 = (const float*)d_in[11]; const float* aff_b2 = (const float*)d_in[12];
    const float* vn_W1  = (const float*)d_in[13]; const float* vn_b1  = (const float*)d_in[14];
    const float* vn_W2  = (const float*)d_in[15]; const float* vn_b2  = (const float*)d_in[16];
    const float* mlp_W1 = (const float*)d_in[17]; const float* mlp_b1 = (const float*)d_in[18];
    const float* mlp_W2 = (const float*)d_in[19]; const float* mlp_b2 = (const float*)d_in[20];
    float* out = (float*)d_out;

    float *p_h2, *p_aff, *p_vn, *p_vn2, *p_gf2, *p_wc, *p_bc;
    int *p_cntm;
    __nv_bfloat16 *p_wt0, *p_wt1;
    cudaGetSymbolAddress((void**)&p_h2,   d_h2);
    cudaGetSymbolAddress((void**)&p_aff,  d_aff);
    cudaGetSymbolAddress((void**)&p_cntm, d_cntm);
    cudaGetSymbolAddress((void**)&p_vn,   d_vn);
    cudaGetSymbolAddress((void**)&p_vn2,  d_vn2);
    cudaGetSymbolAddress((void**)&p_gf2,  d_gf2);
    cudaGetSymbolAddress((void**)&p_wc,   d_wc);
    cudaGetSymbolAddress((void**)&p_bc,   d_bc);
    cudaGetSymbolAddress((void**)&p_wt0,  d_wt0);
    cudaGetSymbolAddress((void**)&p_wt1,  d_wt1);

    const int ATT_SMEM = (2*NPG*HH + HH*33 + NPG*VV) * (int)sizeof(float);
    cudaFuncSetAttribute(k_split,           cudaFuncAttributeMaxDynamicSharedMemorySize, 65536);
    cudaFuncSetAttribute(k_xgcn,            cudaFuncAttributeMaxDynamicSharedMemorySize, XGCN_SMEM);
    cudaFuncSetAttribute(k_mma_gemm<1,1,1>, cudaFuncAttributeMaxDynamicSharedMemorySize, GSM_TOTAL);
    cudaFuncSetAttribute(k_mlp2,            cudaFuncAttributeMaxDynamicSharedMemorySize, GSM_TOTAL);
    cudaFuncSetAttribute(k_att,             cudaFuncAttributeMaxDynamicSharedMemorySize, ATT_SMEM);

    #define WT0(i) (p_wt0 + (size_t)(i) * 16384)
    #define WT1(i) (p_wt1 + (size_t)(i) * 16384)

    // 0) combined weight + splits (slots: 0=Wc, 1=aff1, 2=aff2, 3=vn1, 4=vn2, 5=mlp1)
    k_combine<<<16, 256>>>(W_emb, W_gcn, b_emb, p_wc, p_bc);
    k_split<<<6, 128, 65536>>>(p_wc, aff_W1, aff_W2, vn_W1, vn_W2, mlp_W1, p_wt0, p_wt1);

    // 1) edge count matrix
    cudaMemsetAsync(p_cntm, 0, (size_t)GG * NPG * NPG * sizeof(int));
    k_edges<<<EE/256, 256>>>(ei, p_cntm);

    // 2) fused x-GEMM + GCN -> h2
    k_xgcn<<<NN/128, NT, XGCN_SMEM>>>(x, WT0(0), WT1(0), p_bc, b_gcn, p_cntm, p_h2);

    // 3) affinity MLP (fused 2-layer)
    k_mlp2<<<NN/128, NT, GSM_TOTAL>>>(p_h2, WT0(1), WT1(1), aff_b1,
                                      WT0(2), WT1(2), aff_b2, p_aff);

    // 4) attention vs virtual nodes + weighted pool
    k_att<<<GG, 256, ATT_SMEM>>>(p_h2, p_aff, vemb, eweights, p_vn);

    // 5) virtual-node MLP (fused 2-layer)
    k_mlp2<<<GG*VV/128, NT, GSM_TOTAL>>>(p_vn, WT0(3), WT1(3), vn_b1,
                                         WT0(4), WT1(4), vn_b2, p_vn2);

    // 6) gf = mean over V (fused into A-load) -> relu(gf@mlp_W1+b1) -> head
    k_mma_gemm<1,1,1><<<GG/128, NT, GSM_TOTAL>>>(p_vn2, WT0(5), WT1(5), mlp_b1, p_gf2);
    k_head<<<GG, 128>>>(p_gf2, mlp_W2, mlp_b2, out);
}